// round 9
// baseline (speedup 1.0000x reference)
#include <cuda_runtime.h>
#include <cuda_bf16.h>
#include <math.h>
#include <stdint.h>

#define N_TOT 512
#define D_DIM 512

__device__ float  g_LO[N_TOT * N_TOT];      // lo = -dist/2
__device__ float  g_E[N_TOT * N_TOT];       // exp(lo), diag 0
__device__ uint4  g_Fhi[N_TOT * D_DIM / 8]; // bf16 hi part of F
__device__ uint4  g_Flo[N_TOT * D_DIM / 8]; // bf16 lo part of F
__device__ float  g_norm[N_TOT];
__device__ float  g_ys[N_TOT];
__device__ int    g_perm[N_TOT];
__device__ double g_acc;
__device__ int    g_count;

__device__ __forceinline__ const float* frow(const float* wt, const float* mt, int r) {
    return (r < 256) ? (wt + r * D_DIM) : (mt + (r - 256) * D_DIM);
}
__device__ __forceinline__ float lab(const float* lw, const float* lm, int r) {
    return (r < 256) ? lw[r] : lm[r - 256];
}

__device__ __forceinline__ uint32_t smem_u32(const void* p) {
    uint32_t a;
    asm("{ .reg .u64 t; cvta.to.shared.u64 t, %1; cvt.u32.u64 %0, t; }" : "=r"(a) : "l"(p));
    return a;
}
__device__ __forceinline__ void ldsm4(uint32_t* r, uint32_t addr) {
    asm volatile("ldmatrix.sync.aligned.m8n8.x4.shared.b16 {%0,%1,%2,%3}, [%4];"
                 : "=r"(r[0]), "=r"(r[1]), "=r"(r[2]), "=r"(r[3]) : "r"(addr));
}
__device__ __forceinline__ void mma_bf16(float* c, const uint32_t* a, const uint32_t* b) {
    asm volatile("mma.sync.aligned.m16n8k16.row.col.f32.bf16.bf16.f32 "
                 "{%0,%1,%2,%3}, {%4,%5,%6,%7}, {%8,%9}, {%0,%1,%2,%3};"
                 : "+f"(c[0]), "+f"(c[1]), "+f"(c[2]), "+f"(c[3])
                 : "r"(a[0]), "r"(a[1]), "r"(a[2]), "r"(a[3]), "r"(b[0]), "r"(b[1]));
}
__device__ __forceinline__ void split4(float4 f, uint2& h, uint2& l) {
    __nv_bfloat162 h0 = __floats2bfloat162_rn(f.x, f.y);
    __nv_bfloat162 h1 = __floats2bfloat162_rn(f.z, f.w);
    float2 g0 = __bfloat1622float2(h0), g1 = __bfloat1622float2(h1);
    __nv_bfloat162 l0 = __floats2bfloat162_rn(f.x - g0.x, f.y - g0.y);
    __nv_bfloat162 l1 = __floats2bfloat162_rn(f.z - g1.x, f.w - g1.y);
    h = make_uint2(*(uint32_t*)&h0, *(uint32_t*)&h1);
    l = make_uint2(*(uint32_t*)&l0, *(uint32_t*)&l1);
}

// ---------------------------------------------------------------------------
// Kernel 1: convert F -> bf16 hi/lo + row norms (warp per row, 128 blocks)
//           + 4 sort blocks (rank sort of labels, acc reset).
// ---------------------------------------------------------------------------
__global__ void __launch_bounds__(128)
convert_sort_kernel(const float* __restrict__ wt, const float* __restrict__ mt,
                    const float* __restrict__ lw, const float* __restrict__ lm) {
    __shared__ float ls[N_TOT];
    const int t = threadIdx.x, w = t >> 5, lane = t & 31;
    const int bid = blockIdx.x;

    if (bid < 128) {
        const int row = bid * 4 + w;
        const float4* fr = (const float4*)frow(wt, mt, row);
        float4 f[4];
        #pragma unroll
        for (int r = 0; r < 4; r++) f[r] = fr[lane * 4 + r];
        float na = 0.f;
        #pragma unroll
        for (int r = 0; r < 4; r++) {
            na = fmaf(f[r].x, f[r].x, na); na = fmaf(f[r].y, f[r].y, na);
            na = fmaf(f[r].z, f[r].z, na); na = fmaf(f[r].w, f[r].w, na);
        }
        uint2 h0, l0, h1, l1;
        split4(f[0], h0, l0); split4(f[1], h1, l1);
        g_Fhi[row * 64 + lane * 2] = make_uint4(h0.x, h0.y, h1.x, h1.y);
        g_Flo[row * 64 + lane * 2] = make_uint4(l0.x, l0.y, l1.x, l1.y);
        split4(f[2], h0, l0); split4(f[3], h1, l1);
        g_Fhi[row * 64 + lane * 2 + 1] = make_uint4(h0.x, h0.y, h1.x, h1.y);
        g_Flo[row * 64 + lane * 2 + 1] = make_uint4(l0.x, l0.y, l1.x, l1.y);
        #pragma unroll
        for (int o = 16; o; o >>= 1) na += __shfl_xor_sync(0xffffffffu, na, o);
        if (lane == 0) g_norm[row] = na;
    } else {
        const int sb = bid - 128;
        if (sb == 0 && t == 0) { g_acc = 0.0; g_count = 0; }
        for (int m = t; m < N_TOT; m += 128) ls[m] = lab(lw, lm, m);
        __syncthreads();
        const int e = sb * 128 + t;
        const float ye = ls[e];
        int rank = 0;
        const float4* L4 = (const float4*)ls;
        #pragma unroll 8
        for (int j4 = 0; j4 < N_TOT / 4; j4++) {
            float4 v = L4[j4];
            int j = j4 * 4;
            rank += (v.x < ye) || (v.x == ye && (j + 0) < e);
            rank += (v.y < ye) || (v.y == ye && (j + 1) < e);
            rank += (v.z < ye) || (v.z == ye && (j + 2) < e);
            rank += (v.w < ye) || (v.w == ye && (j + 3) < e);
        }
        g_ys[rank] = ye;
        g_perm[rank] = e;
    }
}

// ---------------------------------------------------------------------------
// Kernel 2: 136 HMMA GEMM blocks (upper-triangle 32x32 tiles, mirror writes)
// ---------------------------------------------------------------------------
#define STRIDE 40
#define BK 32
#define NCHUNK (D_DIM / BK)
#define NBUF 3
#define NTILES 136

struct GemmSmem {
    union {
        unsigned short buf[4][NBUF][32 * STRIDE];   // a_hi, a_lo, b_hi, b_lo
        float stage[32][33];
    } u;
};

__global__ void __launch_bounds__(256)
gemm_kernel() {
    __shared__ GemmSmem sm;
    const int t = threadIdx.x;
    const int bid = blockIdx.x;
    const int w = t >> 5, lane = t & 31;

    int ti = 0, base = 0;
    while (base + (16 - ti) <= bid) { base += 16 - ti; ti++; }
    const int tj = ti + (bid - base);
    const int I = ti * 32, J = tj * 32;

    // load mapping: arr = t>>6 (0:a_hi 1:a_lo 2:b_hi 3:b_lo), 2 uint4/thread
    const int arr = t >> 6;
    const uint4* gsrc = (arr & 1) ? g_Flo : g_Fhi;
    const int rbase = (arr < 2) ? I : J;

    int lrow[2], lq[2];
    #pragma unroll
    for (int r = 0; r < 2; r++) { int u = (t & 63) + r * 64; lrow[r] = u >> 2; lq[r] = u & 3; }

    const int wm = w >> 2, wn = w & 3;
    float c[4] = {};

    const uint32_t sbases[4] = { smem_u32(sm.u.buf[0][0]), smem_u32(sm.u.buf[1][0]),
                                 smem_u32(sm.u.buf[2][0]), smem_u32(sm.u.buf[3][0]) };
    const uint32_t a_hi_b = sbases[0], a_lo_b = sbases[1];
    const uint32_t b_hi_b = sbases[2], b_lo_b = sbases[3];
    const uint32_t mybase = sbases[arr];
    const uint32_t step = 32 * STRIDE * 2;

    const uint32_t a_off = (uint32_t)((wm * 16 + (lane & 15)) * (STRIDE * 2) + ((lane >> 4) & 1) * 16);
    const uint32_t b_off = (uint32_t)((wn * 8 + (lane & 7)) * (STRIDE * 2) + (lane >> 3) * 16);

    uint4 v[2];
    // prologue: chunk0 load+store, chunk1 prefetch
    #pragma unroll
    for (int r = 0; r < 2; r++)
        v[r] = gsrc[(rbase + lrow[r]) * 64 + lq[r]];
    #pragma unroll
    for (int r = 0; r < 2; r++)
        *(uint4*)(sm.u.buf[arr][0] + lrow[r] * STRIDE + lq[r] * 8) = v[r];
    #pragma unroll
    for (int r = 0; r < 2; r++)
        v[r] = gsrc[(rbase + lrow[r]) * 64 + 4 + lq[r]];

    for (int n = 0; n < NCHUNK; n++) {
        const int cur = n % NBUF;
        if (n + 1 < NCHUNK) {
            const int nxt = (n + 1) % NBUF;
            #pragma unroll
            for (int r = 0; r < 2; r++)
                *(uint4*)(sm.u.buf[arr][nxt] + lrow[r] * STRIDE + lq[r] * 8) = v[r];
        }
        if (n + 2 < NCHUNK) {
            #pragma unroll
            for (int r = 0; r < 2; r++)
                v[r] = gsrc[(rbase + lrow[r]) * 64 + (n + 2) * 4 + lq[r]];
        }
        __syncthreads();

        uint32_t Bh[4], Bl[4];
        ldsm4(Bh, b_hi_b + cur * step + b_off);
        ldsm4(Bl, b_lo_b + cur * step + b_off);
        #pragma unroll
        for (int ks = 0; ks < 2; ks++) {
            uint32_t Ah[4], Al[4];
            ldsm4(Ah, a_hi_b + cur * step + a_off + ks * 32);
            ldsm4(Al, a_lo_b + cur * step + a_off + ks * 32);
            mma_bf16(c, Ah, Bh + ks * 2);
            mma_bf16(c, Ah, Bl + ks * 2);
            mma_bf16(c, Al, Bh + ks * 2);
        }
    }
    __syncthreads();   // all ldsm reads done -> stage reuse safe

    // epilogue
    const int r0 = wm * 16 + (lane >> 2);
    const int cL = wn * 8 + (lane & 3) * 2;
    const float ni0 = g_norm[I + r0], ni1 = g_norm[I + r0 + 8];
    const float nj0 = g_norm[J + cL], nj1 = g_norm[J + cL + 1];
    float sq, v00, v01, v10, v11;
    sq = fmaf(-2.f, c[0], ni0 + nj0); v00 = -0.5f * sqrtf(fmaxf(sq, 0.f));
    sq = fmaf(-2.f, c[1], ni0 + nj1); v01 = -0.5f * sqrtf(fmaxf(sq, 0.f));
    sq = fmaf(-2.f, c[2], ni1 + nj0); v10 = -0.5f * sqrtf(fmaxf(sq, 0.f));
    sq = fmaf(-2.f, c[3], ni1 + nj1); v11 = -0.5f * sqrtf(fmaxf(sq, 0.f));
    const int gi0 = I + r0, gi1 = I + r0 + 8, gj0 = J + cL, gj1 = J + cL + 1;
    float e00 = (gi0 == gj0) ? 0.f : __expf(v00);
    float e01 = (gi0 == gj1) ? 0.f : __expf(v01);
    float e10 = (gi1 == gj0) ? 0.f : __expf(v10);
    float e11 = (gi1 == gj1) ? 0.f : __expf(v11);

    *(float2*)&g_LO[gi0 * N_TOT + gj0] = make_float2(v00, v01);
    *(float2*)&g_LO[gi1 * N_TOT + gj0] = make_float2(v10, v11);
    *(float2*)&g_E[gi0 * N_TOT + gj0]  = make_float2(e00, e01);
    *(float2*)&g_E[gi1 * N_TOT + gj0]  = make_float2(e10, e11);

    if (ti != tj) {
        const int mc = t >> 3;          // mirror row (0..31)
        const int rg = (t & 7) * 4;     // 4 source rows
        // pass 1: lo
        sm.u.stage[r0][cL] = v00;     sm.u.stage[r0][cL + 1] = v01;
        sm.u.stage[r0 + 8][cL] = v10; sm.u.stage[r0 + 8][cL + 1] = v11;
        __syncthreads();
        float4 o;
        o.x = sm.u.stage[rg + 0][mc]; o.y = sm.u.stage[rg + 1][mc];
        o.z = sm.u.stage[rg + 2][mc]; o.w = sm.u.stage[rg + 3][mc];
        *(float4*)&g_LO[(J + mc) * N_TOT + I + rg] = o;
        __syncthreads();
        // pass 2: e
        sm.u.stage[r0][cL] = e00;     sm.u.stage[r0][cL + 1] = e01;
        sm.u.stage[r0 + 8][cL] = e10; sm.u.stage[r0 + 8][cL + 1] = e11;
        __syncthreads();
        o.x = sm.u.stage[rg + 0][mc]; o.y = sm.u.stage[rg + 1][mc];
        o.z = sm.u.stage[rg + 2][mc]; o.w = sm.u.stage[rg + 3][mc];
        *(float4*)&g_E[(J + mc) * N_TOT + I + rg] = o;
    }
}

// ---------------------------------------------------------------------------
// Kernel 3: loss, warp per row. 128 blocks x 128 threads. No block barriers
// in the main path; fixed-step branchless searches for full ILP.
// ---------------------------------------------------------------------------
__global__ void __launch_bounds__(128)
loss_kernel(const float* __restrict__ lw, const float* __restrict__ lm,
            float* __restrict__ out) {
    __shared__ float sYs[N_TOT];
    __shared__ int   sPerm[N_TOT];
    __shared__ float sE[4][N_TOT];
    __shared__ float sLO[4][N_TOT];
    __shared__ float sP[4][N_TOT + 4];
    __shared__ float wsum[4];

    const int t = threadIdx.x, w = t >> 5, lane = t & 31;
    for (int x = t; x < N_TOT; x += 128) { sYs[x] = g_ys[x]; sPerm[x] = g_perm[x]; }
    __syncthreads();

    const int row = blockIdx.x * 4 + w;
    const float yi = lab(lw, lm, row);
    const int mbase = lane * 16;

    const float4* Er = (const float4*)(g_E + row * N_TOT);
    const float4* Lr = (const float4*)(g_LO + row * N_TOT);
    #pragma unroll
    for (int r = 0; r < 4; r++) {
        ((float4*)&sE[w][0])[lane * 4 + r]  = Er[lane * 4 + r];
        ((float4*)&sLO[w][0])[lane * 4 + r] = Lr[lane * 4 + r];
    }
    __syncwarp();

    // gather e in sorted order + thread-local exclusive prefix
    float ev[16];
    float run = 0.f;
    #pragma unroll
    for (int r = 0; r < 16; r++) {
        int pm = sPerm[mbase + r];
        float e = (pm == row) ? 0.f : sE[w][pm];
        ev[r] = run;
        run += e;
    }
    // warp scan of thread totals
    float sc = run;
    #pragma unroll
    for (int o = 1; o < 32; o <<= 1) {
        float nv = __shfl_up_sync(0xffffffffu, sc, o);
        if (lane >= o) sc += nv;
    }
    const float S = __shfl_sync(0xffffffffu, sc, 31);
    const float excl = sc - run;
    #pragma unroll
    for (int r = 0; r < 16; r++) sP[w][mbase + r] = excl + ev[r];
    if (lane == 31) sP[w][N_TOT] = S;
    __syncwarp();

    // p = first m with sYs[m] >= yi (uniform across warp)
    int p = 0;
    #pragma unroll
    for (int s = 256; s; s >>= 1) {
        int j = (p + s <= N_TOT) ? (p + s - 1) : (N_TOT - 1);
        if ((p + s <= N_TOT) && (sYs[j] < yi)) p += s;
    }

    float acc = 0.f;
    #pragma unroll 4
    for (int r = 0; r < 16; r++) {
        const int m = mbase + r;
        const int pm = sPerm[m];
        if (pm == row) continue;
        const float tm = fabsf(yi - sYs[m]);
        // a = first j with (j>=p) || (|yi-Y[j]| < tm)
        int a = 0;
        #pragma unroll
        for (int s = 256; s; s >>= 1) {
            int j = (a + s <= N_TOT) ? (a + s - 1) : (N_TOT - 1);
            float d = fabsf(yi - sYs[j]);
            if ((a + s <= N_TOT) && (j < p) && (d >= tm)) a += s;
        }
        // b = first j with (j>=p) && (|yi-Y[j]| >= tm)
        int b = 0;
        #pragma unroll
        for (int s = 256; s; s >>= 1) {
            int j = (b + s <= N_TOT) ? (b + s - 1) : (N_TOT - 1);
            float d = fabsf(yi - sYs[j]);
            if ((b + s <= N_TOT) && ((j < p) || (d < tm))) b += s;
        }
        const float denom = sP[w][a] + (S - sP[w][b]);
        acc += sLO[w][pm] - __logf(denom);
    }

    #pragma unroll
    for (int o = 16; o; o >>= 1) acc += __shfl_xor_sync(0xffffffffu, acc, o);
    if (lane == 0) wsum[w] = acc;
    __syncthreads();
    if (t == 0) {
        float s = wsum[0] + wsum[1] + wsum[2] + wsum[3];
        atomicAdd(&g_acc, (double)s);
        __threadfence();
        int done = atomicAdd(&g_count, 1);
        if (done == gridDim.x - 1) {
            double total = atomicAdd(&g_acc, 0.0);
            out[0] = (float)(-total / (double)(N_TOT * (N_TOT - 1)));
        }
    }
}

extern "C" void kernel_launch(void* const* d_in, const int* in_sizes, int n_in,
                              void* d_out, int out_size) {
    const float* wt = (const float*)d_in[0];
    const float* mt = (const float*)d_in[1];
    const float* lw = (const float*)d_in[2];
    const float* lm = (const float*)d_in[3];
    float* out = (float*)d_out;

    convert_sort_kernel<<<132, 128>>>(wt, mt, lw, lm);
    gemm_kernel<<<NTILES, 256>>>();
    loss_kernel<<<128, 128>>>(lw, lm, out);
}

// round 10
// speedup vs baseline: 1.1042x; 1.1042x over previous
#include <cuda_runtime.h>
#include <cuda_bf16.h>
#include <math.h>
#include <stdint.h>

#define N_TOT 512
#define D_DIM 512

__device__ float  g_LO[N_TOT * N_TOT];   // lo = -dist/2
__device__ uint4  g_Fhi[N_TOT * 64];     // bf16 hi of F (row-major, k-contig)
__device__ uint4  g_Flo[N_TOT * 64];     // bf16 lo of F
__device__ float  g_norm[N_TOT];
__device__ float  g_ys[N_TOT];
__device__ int    g_perm[N_TOT];
__device__ int    g_flags[16];           // row-block converted flags
__device__ double g_acc;
__device__ int    g_count;

__device__ __forceinline__ const float* frow(const float* wt, const float* mt, int r) {
    return (r < 256) ? (wt + r * D_DIM) : (mt + (r - 256) * D_DIM);
}
__device__ __forceinline__ float lab(const float* lw, const float* lm, int r) {
    return (r < 256) ? lw[r] : lm[r - 256];
}

__device__ __forceinline__ uint32_t smem_u32(const void* p) {
    uint32_t a;
    asm("{ .reg .u64 t; cvta.to.shared.u64 t, %1; cvt.u32.u64 %0, t; }" : "=r"(a) : "l"(p));
    return a;
}
__device__ __forceinline__ void ldsm4(uint32_t* r, uint32_t addr) {
    asm volatile("ldmatrix.sync.aligned.m8n8.x4.shared.b16 {%0,%1,%2,%3}, [%4];"
                 : "=r"(r[0]), "=r"(r[1]), "=r"(r[2]), "=r"(r[3]) : "r"(addr));
}
__device__ __forceinline__ void mma_bf16(float* c, const uint32_t* a, const uint32_t* b) {
    asm volatile("mma.sync.aligned.m16n8k16.row.col.f32.bf16.bf16.f32 "
                 "{%0,%1,%2,%3}, {%4,%5,%6,%7}, {%8,%9}, {%0,%1,%2,%3};"
                 : "+f"(c[0]), "+f"(c[1]), "+f"(c[2]), "+f"(c[3])
                 : "r"(a[0]), "r"(a[1]), "r"(a[2]), "r"(a[3]), "r"(b[0]), "r"(b[1]));
}
__device__ __forceinline__ void split4(float4 f, uint2& h, uint2& l) {
    __nv_bfloat162 h0 = __floats2bfloat162_rn(f.x, f.y);
    __nv_bfloat162 h1 = __floats2bfloat162_rn(f.z, f.w);
    float2 g0 = __bfloat1622float2(h0), g1 = __bfloat1622float2(h1);
    __nv_bfloat162 l0 = __floats2bfloat162_rn(f.x - g0.x, f.y - g0.y);
    __nv_bfloat162 l1 = __floats2bfloat162_rn(f.z - g1.x, f.w - g1.y);
    h = make_uint2(*(uint32_t*)&h0, *(uint32_t*)&h1);
    l = make_uint2(*(uint32_t*)&l0, *(uint32_t*)&l1);
}

#define STRIDE 40
#define BK 32
#define NCHUNK (D_DIM / BK)
#define NBUF 3
#define NDIAG 16
#define NOFF 120
#define GRID_G (NDIAG + NOFF + 4)

struct GemmSmem {
    float nA[32];
    union {
        unsigned short buf[4][NBUF][32 * STRIDE];   // a_hi, a_lo, b_hi, b_lo
        float stage[32][33];
        float ls[N_TOT];
    } u;
};

// ---------------------------------------------------------------------------
// Kernel 1: 16 diag tiles (convert once + flag + MMA) | 120 upper tiles (pure
// HMMA from converted bf16, flag-gated) | 4 sort blocks. 256 threads.
// ---------------------------------------------------------------------------
__global__ void __launch_bounds__(256)
gemm_sort_kernel(const float* __restrict__ wt, const float* __restrict__ mt,
                 const float* __restrict__ lw, const float* __restrict__ lm) {
    __shared__ GemmSmem sm;

    const int t = threadIdx.x;
    const int bid = blockIdx.x;
    const int w = t >> 5, lane = t & 31;

    const uint32_t step = 32 * STRIDE * 2;
    const int wm = w >> 2, wn = w & 3;
    const uint32_t a_off = (uint32_t)((wm * 16 + (lane & 15)) * (STRIDE * 2) + ((lane >> 4) & 1) * 16);
    const uint32_t b_off = (uint32_t)((wn * 8 + (lane & 7)) * (STRIDE * 2) + (lane >> 3) * 16);

    if (bid < NDIAG) {
        // ================= diagonal tile: convert rows once + MMA (A==B) ====
        const int I = bid * 32;
        const int g = t >> 3, q = t & 7;
        const float* rp = frow(wt, mt, I + g) + q * 4;
        uint2* fhi2 = (uint2*)g_Fhi;
        uint2* flo2 = (uint2*)g_Flo;
        float nrm = 0.f;
        float c[4] = {};

        const uint32_t hi_b = smem_u32(sm.u.buf[0][0]);
        const uint32_t lo_b = smem_u32(sm.u.buf[1][0]);
        const int srow = (I + g) * 128 + q;   // uint2 index base for this thread

        float4 f = *(const float4*)rp;
        {
            uint2 h, l;
            nrm += f.x*f.x + f.y*f.y + f.z*f.z + f.w*f.w;
            split4(f, h, l);
            *(uint2*)(sm.u.buf[0][0] + g * STRIDE + q * 4) = h;
            *(uint2*)(sm.u.buf[1][0] + g * STRIDE + q * 4) = l;
            fhi2[srow] = h;
            flo2[srow] = l;
        }
        f = *(const float4*)(rp + BK);

        for (int n = 0; n < NCHUNK; n++) {
            const int cur = n % NBUF;
            if (n + 1 < NCHUNK) {
                const int nxt = (n + 1) % NBUF;
                uint2 h, l;
                nrm += f.x*f.x + f.y*f.y + f.z*f.z + f.w*f.w;
                split4(f, h, l);
                *(uint2*)(sm.u.buf[0][nxt] + g * STRIDE + q * 4) = h;
                *(uint2*)(sm.u.buf[1][nxt] + g * STRIDE + q * 4) = l;
                fhi2[srow + (n + 1) * 8] = h;
                flo2[srow + (n + 1) * 8] = l;
            }
            if (n + 2 < NCHUNK) f = *(const float4*)(rp + (n + 2) * BK);
            __syncthreads();

            uint32_t Bh[4], Bl[4];
            ldsm4(Bh, hi_b + cur * step + b_off);
            ldsm4(Bl, lo_b + cur * step + b_off);
            #pragma unroll
            for (int ks = 0; ks < 2; ks++) {
                uint32_t Ah[4], Al[4];
                ldsm4(Ah, hi_b + cur * step + a_off + ks * 32);
                ldsm4(Al, lo_b + cur * step + a_off + ks * 32);
                mma_bf16(c, Ah, Bh + ks * 2);
                mma_bf16(c, Ah, Bl + ks * 2);
                mma_bf16(c, Al, Bh + ks * 2);
            }
        }

        // norms over the 8 q-threads of each row
        nrm += __shfl_xor_sync(0xffffffffu, nrm, 1);
        nrm += __shfl_xor_sync(0xffffffffu, nrm, 2);
        nrm += __shfl_xor_sync(0xffffffffu, nrm, 4);
        if (q == 0) { g_norm[I + g] = nrm; sm.nA[g] = nrm; }
        __syncthreads();
        if (t == 0) { __threadfence(); atomicExch(&g_flags[bid], 1); }

        // epilogue (diagonal tile: direct write only; diag elements unused later)
        const int r0 = wm * 16 + (lane >> 2);
        const int cL = wn * 8 + (lane & 3) * 2;
        const float ni0 = sm.nA[r0], ni1 = sm.nA[r0 + 8];
        const float nj0 = sm.nA[cL], nj1 = sm.nA[cL + 1];
        float sq, v00, v01, v10, v11;
        sq = fmaf(-2.f, c[0], ni0 + nj0); v00 = -0.5f * sqrtf(fmaxf(sq, 0.f));
        sq = fmaf(-2.f, c[1], ni0 + nj1); v01 = -0.5f * sqrtf(fmaxf(sq, 0.f));
        sq = fmaf(-2.f, c[2], ni1 + nj0); v10 = -0.5f * sqrtf(fmaxf(sq, 0.f));
        sq = fmaf(-2.f, c[3], ni1 + nj1); v11 = -0.5f * sqrtf(fmaxf(sq, 0.f));
        *(float2*)&g_LO[(I + r0) * N_TOT + I + cL]     = make_float2(v00, v01);
        *(float2*)&g_LO[(I + r0 + 8) * N_TOT + I + cL] = make_float2(v10, v11);
    } else if (bid < NDIAG + NOFF) {
        // ================= strictly-upper tile: flag-gated pure HMMA ========
        const int idx = bid - NDIAG;
        int ti = 0, base = 0;
        while (base + (15 - ti) <= idx) { base += 15 - ti; ti++; }
        const int tj = ti + 1 + (idx - base);
        const int I = ti * 32, J = tj * 32;

        if (t < 2) {
            const int want = (t == 0) ? ti : tj;
            while (atomicAdd(&g_flags[want], 0) == 0) {}
        }
        __syncthreads();
        __threadfence();

        // load mapping: arr = t>>6 (0:a_hi 1:a_lo 2:b_hi 3:b_lo), 2 uint4/thread
        const int arr = t >> 6;
        const uint4* gsrc = (arr & 1) ? g_Flo : g_Fhi;
        const int rbase = (arr < 2) ? I : J;
        int lrow[2], lq[2];
        #pragma unroll
        for (int r = 0; r < 2; r++) { int u = (t & 63) + r * 64; lrow[r] = u >> 2; lq[r] = u & 3; }

        float c[4] = {};
        const uint32_t a_hi_b = smem_u32(sm.u.buf[0][0]);
        const uint32_t a_lo_b = smem_u32(sm.u.buf[1][0]);
        const uint32_t b_hi_b = smem_u32(sm.u.buf[2][0]);
        const uint32_t b_lo_b = smem_u32(sm.u.buf[3][0]);

        uint4 v[2];
        #pragma unroll
        for (int r = 0; r < 2; r++) v[r] = gsrc[(rbase + lrow[r]) * 64 + lq[r]];
        #pragma unroll
        for (int r = 0; r < 2; r++)
            *(uint4*)(sm.u.buf[arr][0] + lrow[r] * STRIDE + lq[r] * 8) = v[r];
        #pragma unroll
        for (int r = 0; r < 2; r++) v[r] = gsrc[(rbase + lrow[r]) * 64 + 4 + lq[r]];

        for (int n = 0; n < NCHUNK; n++) {
            const int cur = n % NBUF;
            if (n + 1 < NCHUNK) {
                const int nxt = (n + 1) % NBUF;
                #pragma unroll
                for (int r = 0; r < 2; r++)
                    *(uint4*)(sm.u.buf[arr][nxt] + lrow[r] * STRIDE + lq[r] * 8) = v[r];
            }
            if (n + 2 < NCHUNK) {
                #pragma unroll
                for (int r = 0; r < 2; r++)
                    v[r] = gsrc[(rbase + lrow[r]) * 64 + (n + 2) * 4 + lq[r]];
            }
            __syncthreads();

            uint32_t Bh[4], Bl[4];
            ldsm4(Bh, b_hi_b + cur * step + b_off);
            ldsm4(Bl, b_lo_b + cur * step + b_off);
            #pragma unroll
            for (int ks = 0; ks < 2; ks++) {
                uint32_t Ah[4], Al[4];
                ldsm4(Ah, a_hi_b + cur * step + a_off + ks * 32);
                ldsm4(Al, a_lo_b + cur * step + a_off + ks * 32);
                mma_bf16(c, Ah, Bh + ks * 2);
                mma_bf16(c, Ah, Bl + ks * 2);
                mma_bf16(c, Al, Bh + ks * 2);
            }
        }
        __syncthreads();   // ldsm reads complete -> stage reuse safe

        const int r0 = wm * 16 + (lane >> 2);
        const int cL = wn * 8 + (lane & 3) * 2;
        const float ni0 = g_norm[I + r0], ni1 = g_norm[I + r0 + 8];
        const float nj0 = g_norm[J + cL], nj1 = g_norm[J + cL + 1];
        float sq, v00, v01, v10, v11;
        sq = fmaf(-2.f, c[0], ni0 + nj0); v00 = -0.5f * sqrtf(fmaxf(sq, 0.f));
        sq = fmaf(-2.f, c[1], ni0 + nj1); v01 = -0.5f * sqrtf(fmaxf(sq, 0.f));
        sq = fmaf(-2.f, c[2], ni1 + nj0); v10 = -0.5f * sqrtf(fmaxf(sq, 0.f));
        sq = fmaf(-2.f, c[3], ni1 + nj1); v11 = -0.5f * sqrtf(fmaxf(sq, 0.f));
        *(float2*)&g_LO[(I + r0) * N_TOT + J + cL]     = make_float2(v00, v01);
        *(float2*)&g_LO[(I + r0 + 8) * N_TOT + J + cL] = make_float2(v10, v11);

        // mirror via smem transpose
        sm.u.stage[r0][cL] = v00;     sm.u.stage[r0][cL + 1] = v01;
        sm.u.stage[r0 + 8][cL] = v10; sm.u.stage[r0 + 8][cL + 1] = v11;
        __syncthreads();
        const int mc = t >> 3;
        const int rg = (t & 7) * 4;
        float4 o;
        o.x = sm.u.stage[rg + 0][mc]; o.y = sm.u.stage[rg + 1][mc];
        o.z = sm.u.stage[rg + 2][mc]; o.w = sm.u.stage[rg + 3][mc];
        *(float4*)&g_LO[(J + mc) * N_TOT + I + rg] = o;
    } else {
        // ================= 4 sort blocks (2 threads/element) ================
        const int sb = bid - (NDIAG + NOFF);
        if (sb == 0 && t == 0) { g_acc = 0.0; g_count = 0; }
        float* ls = sm.u.ls;
        for (int m = t; m < N_TOT; m += 256) ls[m] = lab(lw, lm, m);
        __syncthreads();
        const int e = sb * 128 + (t >> 1);
        const int half = t & 1;
        const float ye = ls[e];
        int rank = 0;
        const float4* L4 = (const float4*)ls + half * 64;
        const int jbase = half * 256;
        #pragma unroll 4
        for (int j4 = 0; j4 < 64; j4++) {
            float4 vv = L4[j4];
            int j = jbase + j4 * 4;
            rank += (vv.x < ye) || (vv.x == ye && (j + 0) < e);
            rank += (vv.y < ye) || (vv.y == ye && (j + 1) < e);
            rank += (vv.z < ye) || (vv.z == ye && (j + 2) < e);
            rank += (vv.w < ye) || (vv.w == ye && (j + 3) < e);
        }
        rank += __shfl_xor_sync(0xffffffffu, rank, 1);
        if (half == 0) { g_ys[rank] = ye; g_perm[rank] = e; }
    }
}

// ---------------------------------------------------------------------------
// Kernel 2: per-row loss — VERBATIM round-8 numerics (rel_err 0.0) + flag reset
// ---------------------------------------------------------------------------
__global__ void __launch_bounds__(N_TOT)
loss_kernel(const float* __restrict__ lw, const float* __restrict__ lm,
            float* __restrict__ out) {
    __shared__ float sLO[N_TOT];
    __shared__ float sY[N_TOT];
    __shared__ float sD[N_TOT];
    __shared__ float sP[N_TOT + 1];
    __shared__ float warpS[16];
    __shared__ int   sp, spos;

    const int i = blockIdx.x;
    const int m = threadIdx.x;
    const int lane = m & 31, w = m >> 5;

    if (i == 0 && m < 16) g_flags[m] = 0;   // reset for next replay

    sLO[m] = g_LO[i * N_TOT + m];
    sY[m]  = g_ys[m];
    const int pm = g_perm[m];
    const float yi = lab(lw, lm, i);
    if (pm == i) spos = m;
    __syncthreads();

    const float tm = fabsf(yi - sY[m]);
    sD[m] = tm;
    if (m == 0) {
        int lo_ = 0, hi_ = N_TOT;
        while (lo_ < hi_) { int mid = (lo_ + hi_) >> 1; if (sY[mid] >= yi) hi_ = mid; else lo_ = mid + 1; }
        sp = lo_;
    }

    const float lo_s = sLO[pm];
    const float e = (pm == i) ? 0.f : __expf(lo_s);

    float v = e;
    #pragma unroll
    for (int o = 1; o < 32; o <<= 1) {
        float nvl = __shfl_up_sync(0xffffffffu, v, o);
        if (lane >= o) v += nvl;
    }
    if (lane == 31) warpS[w] = v;
    __syncthreads();
    if (w == 0) {
        float s = (lane < 16) ? warpS[lane] : 0.f;
        #pragma unroll
        for (int o = 1; o < 16; o <<= 1) {
            float nvl = __shfl_up_sync(0xffffffffu, s, o);
            if (lane >= o) s += nvl;
        }
        if (lane < 16) warpS[lane] = s;
    }
    __syncthreads();
    const float off = (w > 0) ? warpS[w - 1] : 0.f;
    const float S = warpS[15];
    sP[m] = off + v - e;
    if (m == N_TOT - 1) sP[N_TOT] = off + v;
    __syncthreads();

    const int p = sp;
    int a, b;
    if (m < p) {
        int j = m + 1;
        while (j < p && sD[j] == tm) j++;
        a = j;
        int lo_ = p, hi_ = N_TOT;
        while (lo_ < hi_) { int mid = (lo_ + hi_) >> 1; if (sD[mid] >= tm) hi_ = mid; else lo_ = mid + 1; }
        b = lo_;
    } else {
        int j = m;
        while (j > p && sD[j - 1] == tm) j--;
        b = j;
        int lo_ = 0, hi_ = p;
        while (lo_ < hi_) { int mid = (lo_ + hi_) >> 1; if (sD[mid] < tm) hi_ = mid; else lo_ = mid + 1; }
        a = lo_;
    }

    const float denom = sP[a] + (S - sP[b]);
    float term = (m == spos) ? 0.f : (lo_s - __logf(denom));

    #pragma unroll
    for (int o = 16; o; o >>= 1) term += __shfl_xor_sync(0xffffffffu, term, o);
    __syncthreads();
    if (lane == 0) warpS[w] = term;
    __syncthreads();
    if (m == 0) {
        float s = 0.f;
        #pragma unroll
        for (int qq = 0; qq < 16; qq++) s += warpS[qq];
        atomicAdd(&g_acc, (double)s);
        __threadfence();
        int done = atomicAdd(&g_count, 1);
        if (done == N_TOT - 1) {
            double total = atomicAdd(&g_acc, 0.0);
            out[0] = (float)(-total / (double)(N_TOT * (N_TOT - 1)));
        }
    }
}

extern "C" void kernel_launch(void* const* d_in, const int* in_sizes, int n_in,
                              void* d_out, int out_size) {
    const float* wt = (const float*)d_in[0];
    const float* mt = (const float*)d_in[1];
    const float* lw = (const float*)d_in[2];
    const float* lm = (const float*)d_in[3];
    float* out = (float*)d_out;

    gemm_sort_kernel<<<GRID_G, 256>>>(wt, mt, lw, lm);
    loss_kernel<<<N_TOT, N_TOT>>>(lw, lm, out);
}

// round 11
// speedup vs baseline: 1.2790x; 1.1584x over previous
#include <cuda_runtime.h>
#include <cuda_bf16.h>
#include <math.h>
#include <stdint.h>

#define N_TOT 512
#define D_DIM 512

__device__ float  g_LO[N_TOT * N_TOT];   // lo = -dist/2
__device__ uint4  g_Fhi[N_TOT * 64];     // bf16 hi of F (row-major, k-contig)
__device__ uint4  g_Flo[N_TOT * 64];     // bf16 lo of F
__device__ float  g_norm[N_TOT];
__device__ float  g_ys[N_TOT];
__device__ int    g_perm[N_TOT];
__device__ int    g_flags[16];           // row-block converted flags
__device__ double g_acc;
__device__ int    g_count;

__device__ __forceinline__ const float* frow(const float* wt, const float* mt, int r) {
    return (r < 256) ? (wt + r * D_DIM) : (mt + (r - 256) * D_DIM);
}
__device__ __forceinline__ float lab(const float* lw, const float* lm, int r) {
    return (r < 256) ? lw[r] : lm[r - 256];
}

__device__ __forceinline__ uint32_t smem_u32(const void* p) {
    uint32_t a;
    asm("{ .reg .u64 t; cvta.to.shared.u64 t, %1; cvt.u32.u64 %0, t; }" : "=r"(a) : "l"(p));
    return a;
}
__device__ __forceinline__ void ldsm4(uint32_t* r, uint32_t addr) {
    asm volatile("ldmatrix.sync.aligned.m8n8.x4.shared.b16 {%0,%1,%2,%3}, [%4];"
                 : "=r"(r[0]), "=r"(r[1]), "=r"(r[2]), "=r"(r[3]) : "r"(addr));
}
__device__ __forceinline__ void mma_bf16(float* c, const uint32_t* a, const uint32_t* b) {
    asm volatile("mma.sync.aligned.m16n8k16.row.col.f32.bf16.bf16.f32 "
                 "{%0,%1,%2,%3}, {%4,%5,%6,%7}, {%8,%9}, {%0,%1,%2,%3};"
                 : "+f"(c[0]), "+f"(c[1]), "+f"(c[2]), "+f"(c[3])
                 : "r"(a[0]), "r"(a[1]), "r"(a[2]), "r"(a[3]), "r"(b[0]), "r"(b[1]));
}
__device__ __forceinline__ void split8(float4 f0, float4 f1, uint4& hi, uint4& lo) {
    __nv_bfloat162 h0 = __floats2bfloat162_rn(f0.x, f0.y);
    __nv_bfloat162 h1 = __floats2bfloat162_rn(f0.z, f0.w);
    __nv_bfloat162 h2 = __floats2bfloat162_rn(f1.x, f1.y);
    __nv_bfloat162 h3 = __floats2bfloat162_rn(f1.z, f1.w);
    float2 g0 = __bfloat1622float2(h0), g1 = __bfloat1622float2(h1);
    float2 g2 = __bfloat1622float2(h2), g3 = __bfloat1622float2(h3);
    __nv_bfloat162 l0 = __floats2bfloat162_rn(f0.x - g0.x, f0.y - g0.y);
    __nv_bfloat162 l1 = __floats2bfloat162_rn(f0.z - g1.x, f0.w - g1.y);
    __nv_bfloat162 l2 = __floats2bfloat162_rn(f1.x - g2.x, f1.y - g2.y);
    __nv_bfloat162 l3 = __floats2bfloat162_rn(f1.z - g3.x, f1.w - g3.y);
    hi = make_uint4(*(uint32_t*)&h0, *(uint32_t*)&h1, *(uint32_t*)&h2, *(uint32_t*)&h3);
    lo = make_uint4(*(uint32_t*)&l0, *(uint32_t*)&l1, *(uint32_t*)&l2, *(uint32_t*)&l3);
}

#define STRIDE 40
#define BK 32
#define NCHUNK (D_DIM / BK)
#define NBUF 3
#define NCONV 16
#define NSORT 4
#define NTILES 136
#define GRID_G (NCONV + NSORT + NTILES)

struct GemmSmem {
    union {
        unsigned short buf[4][NBUF][32 * STRIDE];   // a_hi, a_lo, b_hi, b_lo
        float stage[32][33];
        float ls[N_TOT];
    } u;
};

// ---------------------------------------------------------------------------
// Kernel 1: 16 convert blocks (pure convert + flag) | 4 sort blocks |
//           136 triangle HMMA tiles (flag-gated, pure MMA). 256 threads.
// ---------------------------------------------------------------------------
__global__ void __launch_bounds__(256)
gemm_sort_kernel(const float* __restrict__ wt, const float* __restrict__ mt,
                 const float* __restrict__ lw, const float* __restrict__ lm) {
    __shared__ GemmSmem sm;

    const int t = threadIdx.x;
    const int bid = blockIdx.x;
    const int w = t >> 5, lane = t & 31;

    if (bid < NCONV) {
        // ============ convert 32 rows: fp32 -> bf16 hi/lo + norms ============
        const int g = t >> 3, q = t & 7;          // row-in-block, col group
        const int row = bid * 32 + g;
        const float* rp = frow(wt, mt, row);
        float nrm = 0.f;
        #pragma unroll
        for (int n = 0; n < 8; n++) {
            const int col = n * 64 + q * 8;
            float4 f0 = *(const float4*)(rp + col);
            float4 f1 = *(const float4*)(rp + col + 4);
            nrm += f0.x*f0.x + f0.y*f0.y + f0.z*f0.z + f0.w*f0.w
                 + f1.x*f1.x + f1.y*f1.y + f1.z*f1.z + f1.w*f1.w;
            uint4 hi, lo;
            split8(f0, f1, hi, lo);
            g_Fhi[row * 64 + n * 8 + q] = hi;
            g_Flo[row * 64 + n * 8 + q] = lo;
        }
        nrm += __shfl_xor_sync(0xffffffffu, nrm, 1);
        nrm += __shfl_xor_sync(0xffffffffu, nrm, 2);
        nrm += __shfl_xor_sync(0xffffffffu, nrm, 4);
        if (q == 0) g_norm[row] = nrm;
        __syncthreads();
        if (t == 0) { __threadfence(); atomicExch(&g_flags[bid], 1); }
    } else if (bid < NCONV + NSORT) {
        // ============ 4 sort blocks (2 threads/element) =====================
        const int sb = bid - NCONV;
        if (sb == 0 && t == 0) { g_acc = 0.0; g_count = 0; }
        float* ls = sm.u.ls;
        for (int m = t; m < N_TOT; m += 256) ls[m] = lab(lw, lm, m);
        __syncthreads();
        const int e = sb * 128 + (t >> 1);
        const int half = t & 1;
        const float ye = ls[e];
        int rank = 0;
        const float4* L4 = (const float4*)ls + half * 64;
        const int jbase = half * 256;
        #pragma unroll 4
        for (int j4 = 0; j4 < 64; j4++) {
            float4 vv = L4[j4];
            int j = jbase + j4 * 4;
            rank += (vv.x < ye) || (vv.x == ye && (j + 0) < e);
            rank += (vv.y < ye) || (vv.y == ye && (j + 1) < e);
            rank += (vv.z < ye) || (vv.z == ye && (j + 2) < e);
            rank += (vv.w < ye) || (vv.w == ye && (j + 3) < e);
        }
        rank += __shfl_xor_sync(0xffffffffu, rank, 1);
        if (half == 0) { g_ys[rank] = ye; g_perm[rank] = e; }
    } else {
        // ============ triangle tile (ti <= tj): flag-gated pure HMMA ========
        const int idx = bid - (NCONV + NSORT);
        int ti = 0, base = 0;
        while (base + (16 - ti) <= idx) { base += 16 - ti; ti++; }
        const int tj = ti + (idx - base);
        const int I = ti * 32, J = tj * 32;

        if (t < 2) {
            const int want = (t == 0) ? ti : tj;
            while (atomicAdd(&g_flags[want], 0) == 0) {}
        }
        __syncthreads();
        __threadfence();

        const uint32_t step = 32 * STRIDE * 2;
        const int wm = w >> 2, wn = w & 3;
        const uint32_t a_off = (uint32_t)((wm * 16 + (lane & 15)) * (STRIDE * 2) + ((lane >> 4) & 1) * 16);
        const uint32_t b_off = (uint32_t)((wn * 8 + (lane & 7)) * (STRIDE * 2) + (lane >> 3) * 16);

        // load mapping: arr = t>>6 (0:a_hi 1:a_lo 2:b_hi 3:b_lo), 2 uint4/thread
        const int arr = t >> 6;
        const uint4* gsrc = (arr & 1) ? g_Flo : g_Fhi;
        const int rbase = (arr < 2) ? I : J;
        int lrow[2], lq[2];
        #pragma unroll
        for (int r = 0; r < 2; r++) { int u = (t & 63) + r * 64; lrow[r] = u >> 2; lq[r] = u & 3; }

        float c[4] = {};
        const uint32_t a_hi_b = smem_u32(sm.u.buf[0][0]);
        const uint32_t a_lo_b = smem_u32(sm.u.buf[1][0]);
        const uint32_t b_hi_b = smem_u32(sm.u.buf[2][0]);
        const uint32_t b_lo_b = smem_u32(sm.u.buf[3][0]);

        uint4 v[2];
        #pragma unroll
        for (int r = 0; r < 2; r++) v[r] = gsrc[(rbase + lrow[r]) * 64 + lq[r]];
        #pragma unroll
        for (int r = 0; r < 2; r++)
            *(uint4*)(sm.u.buf[arr][0] + lrow[r] * STRIDE + lq[r] * 8) = v[r];
        #pragma unroll
        for (int r = 0; r < 2; r++) v[r] = gsrc[(rbase + lrow[r]) * 64 + 4 + lq[r]];

        for (int n = 0; n < NCHUNK; n++) {
            const int cur = n % NBUF;
            if (n + 1 < NCHUNK) {
                const int nxt = (n + 1) % NBUF;
                #pragma unroll
                for (int r = 0; r < 2; r++)
                    *(uint4*)(sm.u.buf[arr][nxt] + lrow[r] * STRIDE + lq[r] * 8) = v[r];
            }
            if (n + 2 < NCHUNK) {
                #pragma unroll
                for (int r = 0; r < 2; r++)
                    v[r] = gsrc[(rbase + lrow[r]) * 64 + (n + 2) * 4 + lq[r]];
            }
            __syncthreads();

            uint32_t Bh[4], Bl[4];
            ldsm4(Bh, b_hi_b + cur * step + b_off);
            ldsm4(Bl, b_lo_b + cur * step + b_off);
            #pragma unroll
            for (int ks = 0; ks < 2; ks++) {
                uint32_t Ah[4], Al[4];
                ldsm4(Ah, a_hi_b + cur * step + a_off + ks * 32);
                ldsm4(Al, a_lo_b + cur * step + a_off + ks * 32);
                mma_bf16(c, Ah, Bh + ks * 2);
                mma_bf16(c, Ah, Bl + ks * 2);
                mma_bf16(c, Al, Bh + ks * 2);
            }
        }
        __syncthreads();   // ldsm reads complete -> stage reuse safe

        const int r0 = wm * 16 + (lane >> 2);
        const int cL = wn * 8 + (lane & 3) * 2;
        const float ni0 = g_norm[I + r0], ni1 = g_norm[I + r0 + 8];
        const float nj0 = g_norm[J + cL], nj1 = g_norm[J + cL + 1];
        float sq, v00, v01, v10, v11;
        sq = fmaf(-2.f, c[0], ni0 + nj0); v00 = -0.5f * sqrtf(fmaxf(sq, 0.f));
        sq = fmaf(-2.f, c[1], ni0 + nj1); v01 = -0.5f * sqrtf(fmaxf(sq, 0.f));
        sq = fmaf(-2.f, c[2], ni1 + nj0); v10 = -0.5f * sqrtf(fmaxf(sq, 0.f));
        sq = fmaf(-2.f, c[3], ni1 + nj1); v11 = -0.5f * sqrtf(fmaxf(sq, 0.f));
        *(float2*)&g_LO[(I + r0) * N_TOT + J + cL]     = make_float2(v00, v01);
        *(float2*)&g_LO[(I + r0 + 8) * N_TOT + J + cL] = make_float2(v10, v11);

        if (ti != tj) {
            // mirror via smem transpose
            sm.u.stage[r0][cL] = v00;     sm.u.stage[r0][cL + 1] = v01;
            sm.u.stage[r0 + 8][cL] = v10; sm.u.stage[r0 + 8][cL + 1] = v11;
            __syncthreads();
            const int mc = t >> 3;
            const int rg = (t & 7) * 4;
            float4 o;
            o.x = sm.u.stage[rg + 0][mc]; o.y = sm.u.stage[rg + 1][mc];
            o.z = sm.u.stage[rg + 2][mc]; o.w = sm.u.stage[rg + 3][mc];
            *(float4*)&g_LO[(J + mc) * N_TOT + I + rg] = o;
        }
    }
}

// ---------------------------------------------------------------------------
// Kernel 2: per-row loss — VERBATIM round-8 numerics (rel_err 0.0) + flag reset
// ---------------------------------------------------------------------------
__global__ void __launch_bounds__(N_TOT)
loss_kernel(const float* __restrict__ lw, const float* __restrict__ lm,
            float* __restrict__ out) {
    __shared__ float sLO[N_TOT];
    __shared__ float sY[N_TOT];
    __shared__ float sD[N_TOT];
    __shared__ float sP[N_TOT + 1];
    __shared__ float warpS[16];
    __shared__ int   sp, spos;

    const int i = blockIdx.x;
    const int m = threadIdx.x;
    const int lane = m & 31, w = m >> 5;

    if (i == 0 && m < 16) g_flags[m] = 0;   // reset for next replay

    sLO[m] = g_LO[i * N_TOT + m];
    sY[m]  = g_ys[m];
    const int pm = g_perm[m];
    const float yi = lab(lw, lm, i);
    if (pm == i) spos = m;
    __syncthreads();

    const float tm = fabsf(yi - sY[m]);
    sD[m] = tm;
    if (m == 0) {
        int lo_ = 0, hi_ = N_TOT;
        while (lo_ < hi_) { int mid = (lo_ + hi_) >> 1; if (sY[mid] >= yi) hi_ = mid; else lo_ = mid + 1; }
        sp = lo_;
    }

    const float lo_s = sLO[pm];
    const float e = (pm == i) ? 0.f : __expf(lo_s);

    float v = e;
    #pragma unroll
    for (int o = 1; o < 32; o <<= 1) {
        float nvl = __shfl_up_sync(0xffffffffu, v, o);
        if (lane >= o) v += nvl;
    }
    if (lane == 31) warpS[w] = v;
    __syncthreads();
    if (w == 0) {
        float s = (lane < 16) ? warpS[lane] : 0.f;
        #pragma unroll
        for (int o = 1; o < 16; o <<= 1) {
            float nvl = __shfl_up_sync(0xffffffffu, s, o);
            if (lane >= o) s += nvl;
        }
        if (lane < 16) warpS[lane] = s;
    }
    __syncthreads();
    const float off = (w > 0) ? warpS[w - 1] : 0.f;
    const float S = warpS[15];
    sP[m] = off + v - e;
    if (m == N_TOT - 1) sP[N_TOT] = off + v;
    __syncthreads();

    const int p = sp;
    int a, b;
    if (m < p) {
        int j = m + 1;
        while (j < p && sD[j] == tm) j++;
        a = j;
        int lo_ = p, hi_ = N_TOT;
        while (lo_ < hi_) { int mid = (lo_ + hi_) >> 1; if (sD[mid] >= tm) hi_ = mid; else lo_ = mid + 1; }
        b = lo_;
    } else {
        int j = m;
        while (j > p && sD[j - 1] == tm) j--;
        b = j;
        int lo_ = 0, hi_ = p;
        while (lo_ < hi_) { int mid = (lo_ + hi_) >> 1; if (sD[mid] < tm) hi_ = mid; else lo_ = mid + 1; }
        a = lo_;
    }

    const float denom = sP[a] + (S - sP[b]);
    float term = (m == spos) ? 0.f : (lo_s - __logf(denom));

    #pragma unroll
    for (int o = 16; o; o >>= 1) term += __shfl_xor_sync(0xffffffffu, term, o);
    __syncthreads();
    if (lane == 0) warpS[w] = term;
    __syncthreads();
    if (m == 0) {
        float s = 0.f;
        #pragma unroll
        for (int qq = 0; qq < 16; qq++) s += warpS[qq];
        atomicAdd(&g_acc, (double)s);
        __threadfence();
        int done = atomicAdd(&g_count, 1);
        if (done == N_TOT - 1) {
            double total = atomicAdd(&g_acc, 0.0);
            out[0] = (float)(-total / (double)(N_TOT * (N_TOT - 1)));
        }
    }
}

extern "C" void kernel_launch(void* const* d_in, const int* in_sizes, int n_in,
                              void* d_out, int out_size) {
    const float* wt = (const float*)d_in[0];
    const float* mt = (const float*)d_in[1];
    const float* lw = (const float*)d_in[2];
    const float* lm = (const float*)d_in[3];
    float* out = (float*)d_out;

    gemm_sort_kernel<<<GRID_G, 256>>>(wt, mt, lw, lm);
    loss_kernel<<<N_TOT, N_TOT>>>(lw, lm, out);
}

// round 12
// speedup vs baseline: 1.2888x; 1.0076x over previous
#include <cuda_runtime.h>
#include <cuda_bf16.h>
#include <math.h>
#include <stdint.h>

#define N_TOT 512
#define D_DIM 512

__device__ float  g_LO[N_TOT * N_TOT];   // lo = -dist/2
__device__ uint4  g_Fhi[N_TOT * 64];     // bf16 hi of F (row-major, k-contig)
__device__ uint4  g_Flo[N_TOT * 64];     // bf16 lo of F
__device__ float  g_norm[N_TOT];
__device__ float  g_ys[N_TOT];
__device__ int    g_perm[N_TOT];
__device__ int    g_flags[16];           // row-block converted flags
__device__ double g_acc;
__device__ int    g_count;

__device__ __forceinline__ const float* frow(const float* wt, const float* mt, int r) {
    return (r < 256) ? (wt + r * D_DIM) : (mt + (r - 256) * D_DIM);
}
__device__ __forceinline__ float lab(const float* lw, const float* lm, int r) {
    return (r < 256) ? lw[r] : lm[r - 256];
}

__device__ __forceinline__ uint32_t smem_u32(const void* p) {
    uint32_t a;
    asm("{ .reg .u64 t; cvta.to.shared.u64 t, %1; cvt.u32.u64 %0, t; }" : "=r"(a) : "l"(p));
    return a;
}
__device__ __forceinline__ void ldsm4(uint32_t* r, uint32_t addr) {
    asm volatile("ldmatrix.sync.aligned.m8n8.x4.shared.b16 {%0,%1,%2,%3}, [%4];"
                 : "=r"(r[0]), "=r"(r[1]), "=r"(r[2]), "=r"(r[3]) : "r"(addr));
}
__device__ __forceinline__ void mma_bf16(float* c, const uint32_t* a, const uint32_t* b) {
    asm volatile("mma.sync.aligned.m16n8k16.row.col.f32.bf16.bf16.f32 "
                 "{%0,%1,%2,%3}, {%4,%5,%6,%7}, {%8,%9}, {%0,%1,%2,%3};"
                 : "+f"(c[0]), "+f"(c[1]), "+f"(c[2]), "+f"(c[3])
                 : "r"(a[0]), "r"(a[1]), "r"(a[2]), "r"(a[3]), "r"(b[0]), "r"(b[1]));
}
__device__ __forceinline__ void split8(float4 f0, float4 f1, uint4& hi, uint4& lo) {
    __nv_bfloat162 h0 = __floats2bfloat162_rn(f0.x, f0.y);
    __nv_bfloat162 h1 = __floats2bfloat162_rn(f0.z, f0.w);
    __nv_bfloat162 h2 = __floats2bfloat162_rn(f1.x, f1.y);
    __nv_bfloat162 h3 = __floats2bfloat162_rn(f1.z, f1.w);
    float2 g0 = __bfloat1622float2(h0), g1 = __bfloat1622float2(h1);
    float2 g2 = __bfloat1622float2(h2), g3 = __bfloat1622float2(h3);
    __nv_bfloat162 l0 = __floats2bfloat162_rn(f0.x - g0.x, f0.y - g0.y);
    __nv_bfloat162 l1 = __floats2bfloat162_rn(f0.z - g1.x, f0.w - g1.y);
    __nv_bfloat162 l2 = __floats2bfloat162_rn(f1.x - g2.x, f1.y - g2.y);
    __nv_bfloat162 l3 = __floats2bfloat162_rn(f1.z - g3.x, f1.w - g3.y);
    hi = make_uint4(*(uint32_t*)&h0, *(uint32_t*)&h1, *(uint32_t*)&h2, *(uint32_t*)&h3);
    lo = make_uint4(*(uint32_t*)&l0, *(uint32_t*)&l1, *(uint32_t*)&l2, *(uint32_t*)&l3);
}

// SMEM layout (dynamic): 4 arrays (a_hi, a_lo, b_hi, b_lo), each holding all
// 16 k-chunks: chunk stride 2560 B (32 rows x 40 bf16), array stride 40960 B.
#define ROW_B   80
#define CHUNK_B 2560
#define ARR_B   40960
#define SN_OFF  163840
#define SMEM_BYTES (SN_OFF + 256)

#define NCONV 16
#define NSORT 4
#define NOFF  120
#define GRID_G (NCONV + NSORT + NOFF)     // 140 <= 148 SMs: single wave

// ---------------------------------------------------------------------------
// Kernel 1: 16 conv+diag blocks | 4 sort blocks | 120 off-diag HMMA tiles.
// ---------------------------------------------------------------------------
__global__ void __launch_bounds__(256)
gemm_sort_kernel(const float* __restrict__ wt, const float* __restrict__ mt,
                 const float* __restrict__ lw, const float* __restrict__ lm) {
    extern __shared__ char dsm[];

    const int t = threadIdx.x;
    const int bid = blockIdx.x;
    const int w = t >> 5, lane = t & 31;

    const int wm = w >> 2, wn = w & 3;
    const uint32_t a_off = (uint32_t)((wm * 16 + (lane & 15)) * ROW_B + ((lane >> 4) & 1) * 16);
    const uint32_t b_off = (uint32_t)((wn * 8 + (lane & 7)) * ROW_B + (lane >> 3) * 16);

    if (bid < NCONV) {
        // ========== convert 32 rows (global + smem) + flag + diagonal MMA ===
        const int I = bid * 32;
        const int g = t >> 3, q = t & 7;
        const int row = I + g;
        const float* rp = frow(wt, mt, row);
        float* sn = (float*)(dsm + SN_OFF);
        float nrm = 0.f;

        #pragma unroll
        for (int n = 0; n < 8; n++) {
            const int col = n * 64 + q * 8;
            float4 f0 = *(const float4*)(rp + col);
            float4 f1 = *(const float4*)(rp + col + 4);
            nrm += f0.x*f0.x + f0.y*f0.y + f0.z*f0.z + f0.w*f0.w
                 + f1.x*f1.x + f1.y*f1.y + f1.z*f1.z + f1.w*f1.w;
            uint4 hi, lo;
            split8(f0, f1, hi, lo);
            const int c4 = n * 8 + q;
            g_Fhi[row * 64 + c4] = hi;
            g_Flo[row * 64 + c4] = lo;
            const int so = (c4 >> 2) * CHUNK_B + g * ROW_B + (c4 & 3) * 16;
            *(uint4*)(dsm + so) = hi;
            *(uint4*)(dsm + ARR_B + so) = lo;
        }
        nrm += __shfl_xor_sync(0xffffffffu, nrm, 1);
        nrm += __shfl_xor_sync(0xffffffffu, nrm, 2);
        nrm += __shfl_xor_sync(0xffffffffu, nrm, 4);
        if (q == 0) { g_norm[row] = nrm; sn[g] = nrm; }
        __threadfence();
        __syncthreads();
        if (t == 0) atomicExch(&g_flags[bid], 1);

        // diagonal MMA from smem (A == B, arrays 0/1)
        const uint32_t hi_b = smem_u32(dsm);
        const uint32_t lo_b = smem_u32(dsm + ARR_B);
        float c[4] = {};
        for (int n = 0; n < 16; n++) {
            const uint32_t base = n * CHUNK_B;
            uint32_t Bh[4], Bl[4];
            ldsm4(Bh, hi_b + base + b_off);
            ldsm4(Bl, lo_b + base + b_off);
            #pragma unroll
            for (int ks = 0; ks < 2; ks++) {
                uint32_t Ah[4], Al[4];
                ldsm4(Ah, hi_b + base + a_off + ks * 32);
                ldsm4(Al, lo_b + base + a_off + ks * 32);
                mma_bf16(c, Ah, Bh + ks * 2);
                mma_bf16(c, Ah, Bl + ks * 2);
                mma_bf16(c, Al, Bh + ks * 2);
            }
        }

        const int r0 = wm * 16 + (lane >> 2);
        const int cL = wn * 8 + (lane & 3) * 2;
        const float ni0 = sn[r0], ni1 = sn[r0 + 8];
        const float nj0 = sn[cL], nj1 = sn[cL + 1];
        float sq, v00, v01, v10, v11;
        sq = fmaf(-2.f, c[0], ni0 + nj0); v00 = -0.5f * sqrtf(fmaxf(sq, 0.f));
        sq = fmaf(-2.f, c[1], ni0 + nj1); v01 = -0.5f * sqrtf(fmaxf(sq, 0.f));
        sq = fmaf(-2.f, c[2], ni1 + nj0); v10 = -0.5f * sqrtf(fmaxf(sq, 0.f));
        sq = fmaf(-2.f, c[3], ni1 + nj1); v11 = -0.5f * sqrtf(fmaxf(sq, 0.f));
        *(float2*)&g_LO[(I + r0) * N_TOT + I + cL]     = make_float2(v00, v01);
        *(float2*)&g_LO[(I + r0 + 8) * N_TOT + I + cL] = make_float2(v10, v11);
    } else if (bid < NCONV + NSORT) {
        // ========== 4 sort blocks (2 threads/element) =======================
        const int sb = bid - NCONV;
        if (sb == 0 && t == 0) { g_acc = 0.0; g_count = 0; }
        float* ls = (float*)dsm;
        for (int m = t; m < N_TOT; m += 256) ls[m] = lab(lw, lm, m);
        __syncthreads();
        const int e = sb * 128 + (t >> 1);
        const int half = t & 1;
        const float ye = ls[e];
        int rank = 0;
        const float4* L4 = (const float4*)ls + half * 64;
        const int jbase = half * 256;
        #pragma unroll 4
        for (int j4 = 0; j4 < 64; j4++) {
            float4 vv = L4[j4];
            int j = jbase + j4 * 4;
            rank += (vv.x < ye) || (vv.x == ye && (j + 0) < e);
            rank += (vv.y < ye) || (vv.y == ye && (j + 1) < e);
            rank += (vv.z < ye) || (vv.z == ye && (j + 2) < e);
            rank += (vv.w < ye) || (vv.w == ye && (j + 3) < e);
        }
        rank += __shfl_xor_sync(0xffffffffu, rank, 1);
        if (half == 0) { g_ys[rank] = ye; g_perm[rank] = e; }
    } else {
        // ========== off-diag tile (ti < tj): bulk load -> sync-free HMMA ====
        const int idx = bid - (NCONV + NSORT);
        int ti = 0, base = 0;
        while (base + (15 - ti) <= idx) { base += 15 - ti; ti++; }
        const int tj = ti + 1 + (idx - base);
        const int I = ti * 32, J = tj * 32;

        if (t < 2) {
            const int want = (t == 0) ? ti : tj;
            while (atomicAdd(&g_flags[want], 0) == 0) {}
            __threadfence();
        }
        __syncthreads();

        // bulk load: group grp loads one array (32 uint4/thread, 2 MLP-16 rounds)
        const int grp = t >> 6, lt = t & 63;
        const uint4* gsrc = (grp & 1) ? g_Flo : g_Fhi;
        const int rbase = (grp < 2) ? I : J;
        char* abase = dsm + grp * ARR_B;
        #pragma unroll
        for (int r = 0; r < 2; r++) {
            uint4 v[16];
            #pragma unroll
            for (int k = 0; k < 16; k++) {
                const int u = lt + (r * 16 + k) * 64;
                const int chunk = u >> 7, row = (u >> 2) & 31, qq = u & 3;
                v[k] = gsrc[(rbase + row) * 64 + chunk * 4 + qq];
            }
            #pragma unroll
            for (int k = 0; k < 16; k++) {
                const int u = lt + (r * 16 + k) * 64;
                const int chunk = u >> 7, row = (u >> 2) & 31, qq = u & 3;
                *(uint4*)(abase + chunk * CHUNK_B + row * ROW_B + qq * 16) = v[k];
            }
        }
        __syncthreads();

        const uint32_t a_hi_b = smem_u32(dsm);
        const uint32_t a_lo_b = a_hi_b + ARR_B;
        const uint32_t b_hi_b = a_hi_b + 2 * ARR_B;
        const uint32_t b_lo_b = a_hi_b + 3 * ARR_B;
        float c[4] = {};
        #pragma unroll 2
        for (int n = 0; n < 16; n++) {
            const uint32_t cbase = n * CHUNK_B;
            uint32_t Bh[4], Bl[4];
            ldsm4(Bh, b_hi_b + cbase + b_off);
            ldsm4(Bl, b_lo_b + cbase + b_off);
            #pragma unroll
            for (int ks = 0; ks < 2; ks++) {
                uint32_t Ah[4], Al[4];
                ldsm4(Ah, a_hi_b + cbase + a_off + ks * 32);
                ldsm4(Al, a_lo_b + cbase + a_off + ks * 32);
                mma_bf16(c, Ah, Bh + ks * 2);
                mma_bf16(c, Ah, Bl + ks * 2);
                mma_bf16(c, Al, Bh + ks * 2);
            }
        }
        __syncthreads();    // ldsm reads done -> stage overlay safe

        const int r0 = wm * 16 + (lane >> 2);
        const int cL = wn * 8 + (lane & 3) * 2;
        const float ni0 = g_norm[I + r0], ni1 = g_norm[I + r0 + 8];
        const float nj0 = g_norm[J + cL], nj1 = g_norm[J + cL + 1];
        float sq, v00, v01, v10, v11;
        sq = fmaf(-2.f, c[0], ni0 + nj0); v00 = -0.5f * sqrtf(fmaxf(sq, 0.f));
        sq = fmaf(-2.f, c[1], ni0 + nj1); v01 = -0.5f * sqrtf(fmaxf(sq, 0.f));
        sq = fmaf(-2.f, c[2], ni1 + nj0); v10 = -0.5f * sqrtf(fmaxf(sq, 0.f));
        sq = fmaf(-2.f, c[3], ni1 + nj1); v11 = -0.5f * sqrtf(fmaxf(sq, 0.f));
        *(float2*)&g_LO[(I + r0) * N_TOT + J + cL]     = make_float2(v00, v01);
        *(float2*)&g_LO[(I + r0 + 8) * N_TOT + J + cL] = make_float2(v10, v11);

        // mirror via smem transpose (stage overlays the buffers)
        float (*stage)[33] = (float(*)[33])dsm;
        stage[r0][cL] = v00;     stage[r0][cL + 1] = v01;
        stage[r0 + 8][cL] = v10; stage[r0 + 8][cL + 1] = v11;
        __syncthreads();
        const int mc = t >> 3;
        const int rg = (t & 7) * 4;
        float4 o;
        o.x = stage[rg + 0][mc]; o.y = stage[rg + 1][mc];
        o.z = stage[rg + 2][mc]; o.w = stage[rg + 3][mc];
        *(float4*)&g_LO[(J + mc) * N_TOT + I + rg] = o;
    }
}

// ---------------------------------------------------------------------------
// Kernel 2: per-row loss — VERBATIM round-8 numerics (rel_err 0.0) + flag reset
// ---------------------------------------------------------------------------
__global__ void __launch_bounds__(N_TOT)
loss_kernel(const float* __restrict__ lw, const float* __restrict__ lm,
            float* __restrict__ out) {
    __shared__ float sLO[N_TOT];
    __shared__ float sY[N_TOT];
    __shared__ float sD[N_TOT];
    __shared__ float sP[N_TOT + 1];
    __shared__ float warpS[16];
    __shared__ int   sp, spos;

    const int i = blockIdx.x;
    const int m = threadIdx.x;
    const int lane = m & 31, w = m >> 5;

    if (i == 0 && m < 16) g_flags[m] = 0;   // reset for next replay

    sLO[m] = g_LO[i * N_TOT + m];
    sY[m]  = g_ys[m];
    const int pm = g_perm[m];
    const float yi = lab(lw, lm, i);
    if (pm == i) spos = m;
    __syncthreads();

    const float tm = fabsf(yi - sY[m]);
    sD[m] = tm;
    if (m == 0) {
        int lo_ = 0, hi_ = N_TOT;
        while (lo_ < hi_) { int mid = (lo_ + hi_) >> 1; if (sY[mid] >= yi) hi_ = mid; else lo_ = mid + 1; }
        sp = lo_;
    }

    const float lo_s = sLO[pm];
    const float e = (pm == i) ? 0.f : __expf(lo_s);

    float v = e;
    #pragma unroll
    for (int o = 1; o < 32; o <<= 1) {
        float nvl = __shfl_up_sync(0xffffffffu, v, o);
        if (lane >= o) v += nvl;
    }
    if (lane == 31) warpS[w] = v;
    __syncthreads();
    if (w == 0) {
        float s = (lane < 16) ? warpS[lane] : 0.f;
        #pragma unroll
        for (int o = 1; o < 16; o <<= 1) {
            float nvl = __shfl_up_sync(0xffffffffu, s, o);
            if (lane >= o) s += nvl;
        }
        if (lane < 16) warpS[lane] = s;
    }
    __syncthreads();
    const float off = (w > 0) ? warpS[w - 1] : 0.f;
    const float S = warpS[15];
    sP[m] = off + v - e;
    if (m == N_TOT - 1) sP[N_TOT] = off + v;
    __syncthreads();

    const int p = sp;
    int a, b;
    if (m < p) {
        int j = m + 1;
        while (j < p && sD[j] == tm) j++;
        a = j;
        int lo_ = p, hi_ = N_TOT;
        while (lo_ < hi_) { int mid = (lo_ + hi_) >> 1; if (sD[mid] >= tm) hi_ = mid; else lo_ = mid + 1; }
        b = lo_;
    } else {
        int j = m;
        while (j > p && sD[j - 1] == tm) j--;
        b = j;
        int lo_ = 0, hi_ = p;
        while (lo_ < hi_) { int mid = (lo_ + hi_) >> 1; if (sD[mid] < tm) hi_ = mid; else lo_ = mid + 1; }
        a = lo_;
    }

    const float denom = sP[a] + (S - sP[b]);
    float term = (m == spos) ? 0.f : (lo_s - __logf(denom));

    #pragma unroll
    for (int o = 16; o; o >>= 1) term += __shfl_xor_sync(0xffffffffu, term, o);
    __syncthreads();
    if (lane == 0) warpS[w] = term;
    __syncthreads();
    if (m == 0) {
        float s = 0.f;
        #pragma unroll
        for (int qq = 0; qq < 16; qq++) s += warpS[qq];
        atomicAdd(&g_acc, (double)s);
        __threadfence();
        int done = atomicAdd(&g_count, 1);
        if (done == N_TOT - 1) {
            double total = atomicAdd(&g_acc, 0.0);
            out[0] = (float)(-total / (double)(N_TOT * (N_TOT - 1)));
        }
    }
}

extern "C" void kernel_launch(void* const* d_in, const int* in_sizes, int n_in,
                              void* d_out, int out_size) {
    const float* wt = (const float*)d_in[0];
    const float* mt = (const float*)d_in[1];
    const float* lw = (const float*)d_in[2];
    const float* lm = (const float*)d_in[3];
    float* out = (float*)d_out;

    static int attr_set = 0;
    if (!attr_set) {
        cudaFuncSetAttribute(gemm_sort_kernel,
                             cudaFuncAttributeMaxDynamicSharedMemorySize, SMEM_BYTES);
        attr_set = 1;
    }

    gemm_sort_kernel<<<GRID_G, 256, SMEM_BYTES>>>(wt, mt, lw, lm);
    loss_kernel<<<N_TOT, N_TOT>>>(lw, lm, out);
}

// round 13
// speedup vs baseline: 1.2907x; 1.0015x over previous
#include <cuda_runtime.h>
#include <cuda_bf16.h>
#include <math.h>
#include <stdint.h>

#define N_TOT 512
#define D_DIM 512

__device__ __align__(16) float g_LO[N_TOT * N_TOT];   // lo = -dist/2
__device__ __align__(16) float g_ys[N_TOT];           // labels sorted ascending
__device__ __align__(16) int   g_perm[N_TOT];         // g_ys[m] = y[g_perm[m]]
__device__ double g_acc;
__device__ int    g_count;

__device__ __forceinline__ const float* frow(const float* wt, const float* mt, int r) {
    return (r < 256) ? (wt + r * D_DIM) : (mt + (r - 256) * D_DIM);
}
__device__ __forceinline__ float lab(const float* lw, const float* lm, int r) {
    return (r < 256) ? lw[r] : lm[r - 256];
}

// ===================== warp-MMA helpers (HMMA bf16) =====================
__device__ __forceinline__ uint32_t smem_u32(const void* p) {
    uint32_t a;
    asm("{ .reg .u64 t; cvta.to.shared.u64 t, %1; cvt.u32.u64 %0, t; }" : "=r"(a) : "l"(p));
    return a;
}
__device__ __forceinline__ void ldsm4(uint32_t* r, uint32_t addr) {
    asm volatile("ldmatrix.sync.aligned.m8n8.x4.shared.b16 {%0,%1,%2,%3}, [%4];"
                 : "=r"(r[0]), "=r"(r[1]), "=r"(r[2]), "=r"(r[3]) : "r"(addr));
}
__device__ __forceinline__ void mma_bf16(float* c, const uint32_t* a, const uint32_t* b) {
    asm volatile("mma.sync.aligned.m16n8k16.row.col.f32.bf16.bf16.f32 "
                 "{%0,%1,%2,%3}, {%4,%5,%6,%7}, {%8,%9}, {%0,%1,%2,%3};"
                 : "+f"(c[0]), "+f"(c[1]), "+f"(c[2]), "+f"(c[3])
                 : "r"(a[0]), "r"(a[1]), "r"(a[2]), "r"(a[3]), "r"(b[0]), "r"(b[1]));
}

// bf16 split of 4 floats: hi = bf16(x), lo = bf16(x - hi)
__device__ __forceinline__ void split4(float4 f, uint2& h, uint2& l) {
    __nv_bfloat162 h0 = __floats2bfloat162_rn(f.x, f.y);
    __nv_bfloat162 h1 = __floats2bfloat162_rn(f.z, f.w);
    float2 g0 = __bfloat1622float2(h0), g1 = __bfloat1622float2(h1);
    __nv_bfloat162 l0 = __floats2bfloat162_rn(f.x - g0.x, f.y - g0.y);
    __nv_bfloat162 l1 = __floats2bfloat162_rn(f.z - g1.x, f.w - g1.y);
    h = make_uint2(*(uint32_t*)&h0, *(uint32_t*)&h1);
    l = make_uint2(*(uint32_t*)&l0, *(uint32_t*)&l1);
}

#define STRIDE 40          // bf16 elems per smem row (32 data + 8 pad)
#define BK 32
#define NCHUNK (D_DIM / BK)
#define NBUF 3
#define NTILES 136         // 16*17/2 upper-triangle 32x32 tiles
#define GRID_G (NTILES + 4)

struct GemmSmem {
    float nA[32];
    float nB[32];
    union {
        struct {
            unsigned short a_hi[NBUF][32 * STRIDE];
            unsigned short a_lo[NBUF][32 * STRIDE];
            unsigned short b_hi[NBUF][32 * STRIDE];
            unsigned short b_lo[NBUF][32 * STRIDE];
        } buf;
        float stage[32][33];
    } u;
};

// ---------------------------------------------------------------------------
// Kernel 1 (VERBATIM round-8 champion): 136 HMMA triangle tiles + 4 sort blocks
// ---------------------------------------------------------------------------
__global__ void __launch_bounds__(256)
gemm_sort_kernel(const float* __restrict__ wt, const float* __restrict__ mt,
                 const float* __restrict__ lw, const float* __restrict__ lm) {
    __shared__ GemmSmem sm;

    const int t = threadIdx.x;
    const int bid = blockIdx.x;
    const int w = t >> 5, lane = t & 31;

    if (bid < NTILES) {
        int ti = 0, base = 0;
        while (base + (16 - ti) <= bid) { base += 16 - ti; ti++; }
        const int tj = ti + (bid - base);
        const int I = ti * 32, J = tj * 32;

        const int g = t >> 3, q = t & 7;
        const float* arp = frow(wt, mt, I + g) + q * 4;
        const float* brp = frow(wt, mt, J + g) + q * 4;
        float na = 0.f, nb = 0.f;
        const uint32_t se = g * STRIDE + q * 4;

        const int wm = w >> 2, wn = w & 3;
        float c[4] = {};

        const uint32_t a_hi_b = smem_u32(sm.u.buf.a_hi[0]);
        const uint32_t a_lo_b = smem_u32(sm.u.buf.a_lo[0]);
        const uint32_t b_hi_b = smem_u32(sm.u.buf.b_hi[0]);
        const uint32_t b_lo_b = smem_u32(sm.u.buf.b_lo[0]);
        const uint32_t step = 32 * STRIDE * 2;

        const uint32_t a_off = (uint32_t)((wm * 16 + (lane & 15)) * (STRIDE * 2) + ((lane >> 4) & 1) * 16);
        const uint32_t b_off = (uint32_t)((wn * 8 + (lane & 7)) * (STRIDE * 2) + (lane >> 3) * 16);

        float4 Ra, Rb;
        Ra = *(const float4*)arp; Rb = *(const float4*)brp;
        {
            uint2 h, l;
            na += Ra.x*Ra.x + Ra.y*Ra.y + Ra.z*Ra.z + Ra.w*Ra.w;
            split4(Ra, h, l);
            *(uint2*)&sm.u.buf.a_hi[0][se] = h; *(uint2*)&sm.u.buf.a_lo[0][se] = l;
            nb += Rb.x*Rb.x + Rb.y*Rb.y + Rb.z*Rb.z + Rb.w*Rb.w;
            split4(Rb, h, l);
            *(uint2*)&sm.u.buf.b_hi[0][se] = h; *(uint2*)&sm.u.buf.b_lo[0][se] = l;
        }
        Ra = *(const float4*)(arp + BK); Rb = *(const float4*)(brp + BK);

        for (int n = 0; n < NCHUNK; n++) {
            const int cur = n % NBUF;
            if (n + 1 < NCHUNK) {
                const int nxt = (n + 1) % NBUF;
                uint2 h, l;
                na += Ra.x*Ra.x + Ra.y*Ra.y + Ra.z*Ra.z + Ra.w*Ra.w;
                split4(Ra, h, l);
                *(uint2*)&sm.u.buf.a_hi[nxt][se] = h; *(uint2*)&sm.u.buf.a_lo[nxt][se] = l;
                nb += Rb.x*Rb.x + Rb.y*Rb.y + Rb.z*Rb.z + Rb.w*Rb.w;
                split4(Rb, h, l);
                *(uint2*)&sm.u.buf.b_hi[nxt][se] = h; *(uint2*)&sm.u.buf.b_lo[nxt][se] = l;
            }
            if (n + 2 < NCHUNK) {
                const int ko = (n + 2) * BK;
                Ra = *(const float4*)(arp + ko);
                Rb = *(const float4*)(brp + ko);
            }
            __syncthreads();

            uint32_t Bh[4], Bl[4];
            ldsm4(Bh, b_hi_b + cur * step + b_off);
            ldsm4(Bl, b_lo_b + cur * step + b_off);
            #pragma unroll
            for (int ks = 0; ks < 2; ks++) {
                uint32_t Ah[4], Al[4];
                ldsm4(Ah, a_hi_b + cur * step + a_off + ks * 32);
                ldsm4(Al, a_lo_b + cur * step + a_off + ks * 32);
                mma_bf16(c, Ah, Bh + ks * 2);
                mma_bf16(c, Ah, Bl + ks * 2);
                mma_bf16(c, Al, Bh + ks * 2);
            }
        }

        na += __shfl_xor_sync(0xffffffffu, na, 1);
        na += __shfl_xor_sync(0xffffffffu, na, 2);
        na += __shfl_xor_sync(0xffffffffu, na, 4);
        nb += __shfl_xor_sync(0xffffffffu, nb, 1);
        nb += __shfl_xor_sync(0xffffffffu, nb, 2);
        nb += __shfl_xor_sync(0xffffffffu, nb, 4);
        __syncthreads();
        if (q == 0) { sm.nA[g] = na; sm.nB[g] = nb; }
        __syncthreads();

        const int r0 = wm * 16 + (lane >> 2);
        const int cL = wn * 8 + (lane & 3) * 2;
        const float ni0 = sm.nA[r0], ni1 = sm.nA[r0 + 8];
        const float nj0 = sm.nB[cL], nj1 = sm.nB[cL + 1];
        float sq, v00, v01, v10, v11;
        sq = fmaf(-2.f, c[0], ni0 + nj0); v00 = -0.5f * sqrtf(fmaxf(sq, 0.f));
        sq = fmaf(-2.f, c[1], ni0 + nj1); v01 = -0.5f * sqrtf(fmaxf(sq, 0.f));
        sq = fmaf(-2.f, c[2], ni1 + nj0); v10 = -0.5f * sqrtf(fmaxf(sq, 0.f));
        sq = fmaf(-2.f, c[3], ni1 + nj1); v11 = -0.5f * sqrtf(fmaxf(sq, 0.f));
        *(float2*)&g_LO[(I + r0) * N_TOT + J + cL]     = make_float2(v00, v01);
        *(float2*)&g_LO[(I + r0 + 8) * N_TOT + J + cL] = make_float2(v10, v11);

        if (ti != tj) {
            sm.u.stage[r0][cL] = v00;     sm.u.stage[r0][cL + 1] = v01;
            sm.u.stage[r0 + 8][cL] = v10; sm.u.stage[r0 + 8][cL + 1] = v11;
            __syncthreads();
            const int mc = t >> 3;
            const int rg = (t & 7) * 4;
            float4 o;
            o.x = sm.u.stage[rg + 0][mc]; o.y = sm.u.stage[rg + 1][mc];
            o.z = sm.u.stage[rg + 2][mc]; o.w = sm.u.stage[rg + 3][mc];
            *(float4*)&g_LO[(J + mc) * N_TOT + I + rg] = o;
        }
    } else {
        const int sb = bid - NTILES;
        if (sb == 0 && t == 0) { g_acc = 0.0; g_count = 0; }
        float* ls = (float*)&sm;
        for (int m = t; m < N_TOT; m += 256) ls[m] = lab(lw, lm, m);
        __syncthreads();
        const int e = sb * 128 + (t >> 1);
        const int half = t & 1;
        const float ye = ls[e];
        int rank = 0;
        const float4* L4 = (const float4*)ls + half * 64;
        const int jbase = half * 256;
        #pragma unroll 4
        for (int j4 = 0; j4 < 64; j4++) {
            float4 v = L4[j4];
            int j = jbase + j4 * 4;
            rank += (v.x < ye) || (v.x == ye && (j + 0) < e);
            rank += (v.y < ye) || (v.y == ye && (j + 1) < e);
            rank += (v.z < ye) || (v.z == ye && (j + 2) < e);
            rank += (v.w < ye) || (v.w == ye && (j + 3) < e);
        }
        rank += __shfl_xor_sync(0xffffffffu, rank, 1);
        if (half == 0) { g_ys[rank] = ye; g_perm[rank] = e; }
    }
}

// ---------------------------------------------------------------------------
// Kernel 2: loss — round-8 interval logic, restructured to 128 threads/block
// (4 consecutive sorted positions per thread) for ILP + cheap barriers.
// ---------------------------------------------------------------------------
__global__ void __launch_bounds__(128)
loss_kernel(const float* __restrict__ lw, const float* __restrict__ lm,
            float* __restrict__ out) {
    __shared__ float sLO[N_TOT];
    __shared__ float sY[N_TOT];
    __shared__ float sD[N_TOT];
    __shared__ float sP[N_TOT + 1];
    __shared__ float warpS[4];
    __shared__ int   sp;

    const int i = blockIdx.x;
    const int t = threadIdx.x;
    const int lane = t & 31, w = t >> 5;
    const float yi = lab(lw, lm, i);

    ((float4*)sLO)[t] = ((const float4*)(g_LO + i * N_TOT))[t];
    ((float4*)sY)[t]  = ((const float4*)g_ys)[t];
    const int4 pm4 = ((const int4*)g_perm)[t];
    const int pm[4] = { pm4.x, pm4.y, pm4.z, pm4.w };

    float tm4[4];
    #pragma unroll
    for (int r = 0; r < 4; r++) {
        tm4[r] = fabsf(yi - sY[4 * t + r]);
        sD[4 * t + r] = tm4[r];
    }
    __syncthreads();

    // e values in sorted order (diagonal -> 0) + thread-local exclusive prefix
    float ev[4], run = 0.f;
    #pragma unroll
    for (int r = 0; r < 4; r++) {
        float e = (pm[r] == i) ? 0.f : __expf(sLO[pm[r]]);
        ev[r] = run;
        run += e;
    }
    // warp inclusive scan of thread totals
    float sc = run;
    #pragma unroll
    for (int o = 1; o < 32; o <<= 1) {
        float nv = __shfl_up_sync(0xffffffffu, sc, o);
        if (lane >= o) sc += nv;
    }
    if (lane == 31) warpS[w] = sc;
    if (t == 0) {
        int lo_ = 0, hi_ = N_TOT;
        while (lo_ < hi_) { int mid = (lo_ + hi_) >> 1; if (sY[mid] >= yi) hi_ = mid; else lo_ = mid + 1; }
        sp = lo_;
    }
    __syncthreads();

    const float w0 = warpS[0], w1 = warpS[1], w2 = warpS[2], w3 = warpS[3];
    const float woff = (w > 0 ? w0 : 0.f) + (w > 1 ? w1 : 0.f) + (w > 2 ? w2 : 0.f);
    const float S = ((w0 + w1) + w2) + w3;
    const float base = woff + (sc - run);
    #pragma unroll
    for (int r = 0; r < 4; r++) sP[4 * t + r] = base + ev[r];
    if (t == 127) sP[N_TOT] = woff + sc;   // == S bitwise (w3 written by this thread)
    __syncthreads();

    const int p = sp;
    float acc = 0.f;
    #pragma unroll
    for (int r = 0; r < 4; r++) {
        const int m = 4 * t + r;
        if (pm[r] == i) continue;
        const float tm = tm4[r];
        int a, b;
        if (m < p) {
            int j = m + 1;
            while (j < p && sD[j] == tm) j++;
            a = j;
            int lo_ = p, hi_ = N_TOT;
            while (lo_ < hi_) { int mid = (lo_ + hi_) >> 1; if (sD[mid] >= tm) hi_ = mid; else lo_ = mid + 1; }
            b = lo_;
        } else {
            int j = m;
            while (j > p && sD[j - 1] == tm) j--;
            b = j;
            int lo_ = 0, hi_ = p;
            while (lo_ < hi_) { int mid = (lo_ + hi_) >> 1; if (sD[mid] < tm) hi_ = mid; else lo_ = mid + 1; }
            a = lo_;
        }
        const float denom = sP[a] + (S - sP[b]);
        acc += sLO[pm[r]] - __logf(denom);
    }

    #pragma unroll
    for (int o = 16; o; o >>= 1) acc += __shfl_xor_sync(0xffffffffu, acc, o);
    __syncthreads();            // protect warpS reuse
    if (lane == 0) warpS[w] = acc;
    __syncthreads();
    if (t == 0) {
        float s = ((warpS[0] + warpS[1]) + warpS[2]) + warpS[3];
        atomicAdd(&g_acc, (double)s);
        __threadfence();
        int done = atomicAdd(&g_count, 1);
        if (done == N_TOT - 1) {
            double total = atomicAdd(&g_acc, 0.0);
            out[0] = (float)(-total / (double)(N_TOT * (N_TOT - 1)));
        }
    }
}

extern "C" void kernel_launch(void* const* d_in, const int* in_sizes, int n_in,
                              void* d_out, int out_size) {
    const float* wt = (const float*)d_in[0];
    const float* mt = (const float*)d_in[1];
    const float* lw = (const float*)d_in[2];
    const float* lm = (const float*)d_in[3];
    float* out = (float*)d_out;

    gemm_sort_kernel<<<GRID_G, 256>>>(wt, mt, lw, lm);
    loss_kernel<<<N_TOT, 128>>>(lw, lm, out);
}

// round 14
// speedup vs baseline: 1.4181x; 1.0987x over previous
#include <cuda_runtime.h>
#include <cuda_bf16.h>
#include <math.h>
#include <stdint.h>

#define N_TOT 512
#define D_DIM 512

__device__ __align__(16) float g_LO[N_TOT * N_TOT];   // lo = -dist/2
__device__ __align__(16) float g_ys[N_TOT];           // labels sorted ascending
__device__ __align__(16) int   g_perm[N_TOT];         // g_ys[m] = y[g_perm[m]]
__device__ double g_acc;
__device__ int    g_count;

__device__ __forceinline__ const float* frow(const float* wt, const float* mt, int r) {
    return (r < 256) ? (wt + r * D_DIM) : (mt + (r - 256) * D_DIM);
}
__device__ __forceinline__ float lab(const float* lw, const float* lm, int r) {
    return (r < 256) ? lw[r] : lm[r - 256];
}

// ===================== warp-MMA helpers (HMMA bf16) =====================
__device__ __forceinline__ uint32_t smem_u32(const void* p) {
    uint32_t a;
    asm("{ .reg .u64 t; cvta.to.shared.u64 t, %1; cvt.u32.u64 %0, t; }" : "=r"(a) : "l"(p));
    return a;
}
__device__ __forceinline__ void ldsm4(uint32_t* r, uint32_t addr) {
    asm volatile("ldmatrix.sync.aligned.m8n8.x4.shared.b16 {%0,%1,%2,%3}, [%4];"
                 : "=r"(r[0]), "=r"(r[1]), "=r"(r[2]), "=r"(r[3]) : "r"(addr));
}
__device__ __forceinline__ void mma_bf16(float* c, const uint32_t* a, const uint32_t* b) {
    asm volatile("mma.sync.aligned.m16n8k16.row.col.f32.bf16.bf16.f32 "
                 "{%0,%1,%2,%3}, {%4,%5,%6,%7}, {%8,%9}, {%0,%1,%2,%3};"
                 : "+f"(c[0]), "+f"(c[1]), "+f"(c[2]), "+f"(c[3])
                 : "r"(a[0]), "r"(a[1]), "r"(a[2]), "r"(a[3]), "r"(b[0]), "r"(b[1]));
}

// bf16 split of 4 floats: hi = bf16(x), lo = bf16(x - hi)
__device__ __forceinline__ void split4(float4 f, uint2& h, uint2& l) {
    __nv_bfloat162 h0 = __floats2bfloat162_rn(f.x, f.y);
    __nv_bfloat162 h1 = __floats2bfloat162_rn(f.z, f.w);
    float2 g0 = __bfloat1622float2(h0), g1 = __bfloat1622float2(h1);
    __nv_bfloat162 l0 = __floats2bfloat162_rn(f.x - g0.x, f.y - g0.y);
    __nv_bfloat162 l1 = __floats2bfloat162_rn(f.z - g1.x, f.w - g1.y);
    h = make_uint2(*(uint32_t*)&h0, *(uint32_t*)&h1);
    l = make_uint2(*(uint32_t*)&l0, *(uint32_t*)&l1);
}

#define STRIDE 40          // bf16 elems per smem row (32 data + 8 pad)
#define BK 32
#define NCHUNK (D_DIM / BK)
#define NBUF 3
#define NTILES 136         // 16*17/2 upper-triangle 32x32 tiles
#define GRID_G (NTILES + 4)

struct GemmSmem {
    float nA[32];
    float nB[32];
    union {
        struct {
            unsigned short a_hi[NBUF][32 * STRIDE];
            unsigned short a_lo[NBUF][32 * STRIDE];
            unsigned short b_hi[NBUF][32 * STRIDE];
            unsigned short b_lo[NBUF][32 * STRIDE];
        } buf;
        float stage[32][33];
    } u;
};

// ---------------------------------------------------------------------------
// Kernel 1 (VERBATIM round-8 champion): 136 HMMA triangle tiles + 4 sort blocks
// ---------------------------------------------------------------------------
__global__ void __launch_bounds__(256)
gemm_sort_kernel(const float* __restrict__ wt, const float* __restrict__ mt,
                 const float* __restrict__ lw, const float* __restrict__ lm) {
    __shared__ GemmSmem sm;

    const int t = threadIdx.x;
    const int bid = blockIdx.x;
    const int w = t >> 5, lane = t & 31;

    if (bid < NTILES) {
        int ti = 0, base = 0;
        while (base + (16 - ti) <= bid) { base += 16 - ti; ti++; }
        const int tj = ti + (bid - base);
        const int I = ti * 32, J = tj * 32;

        const int g = t >> 3, q = t & 7;
        const float* arp = frow(wt, mt, I + g) + q * 4;
        const float* brp = frow(wt, mt, J + g) + q * 4;
        float na = 0.f, nb = 0.f;
        const uint32_t se = g * STRIDE + q * 4;

        const int wm = w >> 2, wn = w & 3;
        float c[4] = {};

        const uint32_t a_hi_b = smem_u32(sm.u.buf.a_hi[0]);
        const uint32_t a_lo_b = smem_u32(sm.u.buf.a_lo[0]);
        const uint32_t b_hi_b = smem_u32(sm.u.buf.b_hi[0]);
        const uint32_t b_lo_b = smem_u32(sm.u.buf.b_lo[0]);
        const uint32_t step = 32 * STRIDE * 2;

        const uint32_t a_off = (uint32_t)((wm * 16 + (lane & 15)) * (STRIDE * 2) + ((lane >> 4) & 1) * 16);
        const uint32_t b_off = (uint32_t)((wn * 8 + (lane & 7)) * (STRIDE * 2) + (lane >> 3) * 16);

        float4 Ra, Rb;
        Ra = *(const float4*)arp; Rb = *(const float4*)brp;
        {
            uint2 h, l;
            na += Ra.x*Ra.x + Ra.y*Ra.y + Ra.z*Ra.z + Ra.w*Ra.w;
            split4(Ra, h, l);
            *(uint2*)&sm.u.buf.a_hi[0][se] = h; *(uint2*)&sm.u.buf.a_lo[0][se] = l;
            nb += Rb.x*Rb.x + Rb.y*Rb.y + Rb.z*Rb.z + Rb.w*Rb.w;
            split4(Rb, h, l);
            *(uint2*)&sm.u.buf.b_hi[0][se] = h; *(uint2*)&sm.u.buf.b_lo[0][se] = l;
        }
        Ra = *(const float4*)(arp + BK); Rb = *(const float4*)(brp + BK);

        for (int n = 0; n < NCHUNK; n++) {
            const int cur = n % NBUF;
            if (n + 1 < NCHUNK) {
                const int nxt = (n + 1) % NBUF;
                uint2 h, l;
                na += Ra.x*Ra.x + Ra.y*Ra.y + Ra.z*Ra.z + Ra.w*Ra.w;
                split4(Ra, h, l);
                *(uint2*)&sm.u.buf.a_hi[nxt][se] = h; *(uint2*)&sm.u.buf.a_lo[nxt][se] = l;
                nb += Rb.x*Rb.x + Rb.y*Rb.y + Rb.z*Rb.z + Rb.w*Rb.w;
                split4(Rb, h, l);
                *(uint2*)&sm.u.buf.b_hi[nxt][se] = h; *(uint2*)&sm.u.buf.b_lo[nxt][se] = l;
            }
            if (n + 2 < NCHUNK) {
                const int ko = (n + 2) * BK;
                Ra = *(const float4*)(arp + ko);
                Rb = *(const float4*)(brp + ko);
            }
            __syncthreads();

            uint32_t Bh[4], Bl[4];
            ldsm4(Bh, b_hi_b + cur * step + b_off);
            ldsm4(Bl, b_lo_b + cur * step + b_off);
            #pragma unroll
            for (int ks = 0; ks < 2; ks++) {
                uint32_t Ah[4], Al[4];
                ldsm4(Ah, a_hi_b + cur * step + a_off + ks * 32);
                ldsm4(Al, a_lo_b + cur * step + a_off + ks * 32);
                mma_bf16(c, Ah, Bh + ks * 2);
                mma_bf16(c, Ah, Bl + ks * 2);
                mma_bf16(c, Al, Bh + ks * 2);
            }
        }

        na += __shfl_xor_sync(0xffffffffu, na, 1);
        na += __shfl_xor_sync(0xffffffffu, na, 2);
        na += __shfl_xor_sync(0xffffffffu, na, 4);
        nb += __shfl_xor_sync(0xffffffffu, nb, 1);
        nb += __shfl_xor_sync(0xffffffffu, nb, 2);
        nb += __shfl_xor_sync(0xffffffffu, nb, 4);
        __syncthreads();
        if (q == 0) { sm.nA[g] = na; sm.nB[g] = nb; }
        __syncthreads();

        const int r0 = wm * 16 + (lane >> 2);
        const int cL = wn * 8 + (lane & 3) * 2;
        const float ni0 = sm.nA[r0], ni1 = sm.nA[r0 + 8];
        const float nj0 = sm.nB[cL], nj1 = sm.nB[cL + 1];
        float sq, v00, v01, v10, v11;
        sq = fmaf(-2.f, c[0], ni0 + nj0); v00 = -0.5f * sqrtf(fmaxf(sq, 0.f));
        sq = fmaf(-2.f, c[1], ni0 + nj1); v01 = -0.5f * sqrtf(fmaxf(sq, 0.f));
        sq = fmaf(-2.f, c[2], ni1 + nj0); v10 = -0.5f * sqrtf(fmaxf(sq, 0.f));
        sq = fmaf(-2.f, c[3], ni1 + nj1); v11 = -0.5f * sqrtf(fmaxf(sq, 0.f));
        *(float2*)&g_LO[(I + r0) * N_TOT + J + cL]     = make_float2(v00, v01);
        *(float2*)&g_LO[(I + r0 + 8) * N_TOT + J + cL] = make_float2(v10, v11);

        if (ti != tj) {
            sm.u.stage[r0][cL] = v00;     sm.u.stage[r0][cL + 1] = v01;
            sm.u.stage[r0 + 8][cL] = v10; sm.u.stage[r0 + 8][cL + 1] = v11;
            __syncthreads();
            const int mc = t >> 3;
            const int rg = (t & 7) * 4;
            float4 o;
            o.x = sm.u.stage[rg + 0][mc]; o.y = sm.u.stage[rg + 1][mc];
            o.z = sm.u.stage[rg + 2][mc]; o.w = sm.u.stage[rg + 3][mc];
            *(float4*)&g_LO[(J + mc) * N_TOT + I + rg] = o;
        }
    } else {
        const int sb = bid - NTILES;
        if (sb == 0 && t == 0) { g_acc = 0.0; g_count = 0; }
        float* ls = (float*)&sm;
        for (int m = t; m < N_TOT; m += 256) ls[m] = lab(lw, lm, m);
        __syncthreads();
        const int e = sb * 128 + (t >> 1);
        const int half = t & 1;
        const float ye = ls[e];
        int rank = 0;
        const float4* L4 = (const float4*)ls + half * 64;
        const int jbase = half * 256;
        #pragma unroll 4
        for (int j4 = 0; j4 < 64; j4++) {
            float4 v = L4[j4];
            int j = jbase + j4 * 4;
            rank += (v.x < ye) || (v.x == ye && (j + 0) < e);
            rank += (v.y < ye) || (v.y == ye && (j + 1) < e);
            rank += (v.z < ye) || (v.z == ye && (j + 2) < e);
            rank += (v.w < ye) || (v.w == ye && (j + 3) < e);
        }
        rank += __shfl_xor_sync(0xffffffffu, rank, 1);
        if (half == 0) { g_ys[rank] = ye; g_perm[rank] = e; }
    }
}

// ---------------------------------------------------------------------------
// Kernel 2: loss — round-8 per-row numerics (bitwise identical per row),
// 2 rows per 512-thread block (grid 256) for 2x ILP per barrier interval.
// ---------------------------------------------------------------------------
__global__ void __launch_bounds__(N_TOT)
loss_kernel(const float* __restrict__ lw, const float* __restrict__ lm,
            float* __restrict__ out) {
    __shared__ float sLO0[N_TOT], sLO1[N_TOT];
    __shared__ float sY[N_TOT];
    __shared__ float sD0[N_TOT], sD1[N_TOT];
    __shared__ float sP0[N_TOT + 1], sP1[N_TOT + 1];
    __shared__ float warpS0[16], warpS1[16];
    __shared__ int   sp0, sp1;

    const int i0 = blockIdx.x * 2;
    const int i1 = i0 + 1;
    const int m = threadIdx.x;
    const int lane = m & 31, w = m >> 5;

    sLO0[m] = g_LO[i0 * N_TOT + m];
    sLO1[m] = g_LO[i1 * N_TOT + m];
    sY[m]   = g_ys[m];
    const int pm = g_perm[m];
    const float yi0 = lab(lw, lm, i0);
    const float yi1 = lab(lw, lm, i1);
    __syncthreads();

    const float tm0 = fabsf(yi0 - sY[m]);
    const float tm1 = fabsf(yi1 - sY[m]);
    sD0[m] = tm0;
    sD1[m] = tm1;
    if (m == 0) {
        int lo_ = 0, hi_ = N_TOT;
        while (lo_ < hi_) { int mid = (lo_ + hi_) >> 1; if (sY[mid] >= yi0) hi_ = mid; else lo_ = mid + 1; }
        sp0 = lo_;
    }
    if (m == 1) {
        int lo_ = 0, hi_ = N_TOT;
        while (lo_ < hi_) { int mid = (lo_ + hi_) >> 1; if (sY[mid] >= yi1) hi_ = mid; else lo_ = mid + 1; }
        sp1 = lo_;
    }

    const float lo_s0 = sLO0[pm];
    const float lo_s1 = sLO1[pm];
    const float e0 = (pm == i0) ? 0.f : __expf(lo_s0);
    const float e1 = (pm == i1) ? 0.f : __expf(lo_s1);

    // per-row warp scans (identical arithmetic to round 8, two independent chains)
    float v0 = e0, v1 = e1;
    #pragma unroll
    for (int o = 1; o < 32; o <<= 1) {
        float n0 = __shfl_up_sync(0xffffffffu, v0, o);
        float n1 = __shfl_up_sync(0xffffffffu, v1, o);
        if (lane >= o) { v0 += n0; v1 += n1; }
    }
    if (lane == 31) { warpS0[w] = v0; warpS1[w] = v1; }
    __syncthreads();
    if (w == 0) {
        float s = (lane < 16) ? warpS0[lane] : 0.f;
        #pragma unroll
        for (int o = 1; o < 16; o <<= 1) {
            float nv = __shfl_up_sync(0xffffffffu, s, o);
            if (lane >= o) s += nv;
        }
        if (lane < 16) warpS0[lane] = s;
    }
    if (w == 1) {
        float s = (lane < 16) ? warpS1[lane] : 0.f;
        #pragma unroll
        for (int o = 1; o < 16; o <<= 1) {
            float nv = __shfl_up_sync(0xffffffffu, s, o);
            if (lane >= o) s += nv;
        }
        if (lane < 16) warpS1[lane] = s;
    }
    __syncthreads();
    const float off0 = (w > 0) ? warpS0[w - 1] : 0.f;
    const float off1 = (w > 0) ? warpS1[w - 1] : 0.f;
    const float S0 = warpS0[15];
    const float S1 = warpS1[15];
    sP0[m] = off0 + v0 - e0;
    sP1[m] = off1 + v1 - e1;
    if (m == N_TOT - 1) { sP0[N_TOT] = off0 + v0; sP1[N_TOT] = off1 + v1; }
    __syncthreads();

    // row 0 interval (round-8 logic verbatim)
    const int p0 = sp0;
    int a0, b0;
    if (m < p0) {
        int j = m + 1;
        while (j < p0 && sD0[j] == tm0) j++;
        a0 = j;
        int lo_ = p0, hi_ = N_TOT;
        while (lo_ < hi_) { int mid = (lo_ + hi_) >> 1; if (sD0[mid] >= tm0) hi_ = mid; else lo_ = mid + 1; }
        b0 = lo_;
    } else {
        int j = m;
        while (j > p0 && sD0[j - 1] == tm0) j--;
        b0 = j;
        int lo_ = 0, hi_ = p0;
        while (lo_ < hi_) { int mid = (lo_ + hi_) >> 1; if (sD0[mid] < tm0) hi_ = mid; else lo_ = mid + 1; }
        a0 = lo_;
    }
    // row 1 interval
    const int p1 = sp1;
    int a1, b1;
    if (m < p1) {
        int j = m + 1;
        while (j < p1 && sD1[j] == tm1) j++;
        a1 = j;
        int lo_ = p1, hi_ = N_TOT;
        while (lo_ < hi_) { int mid = (lo_ + hi_) >> 1; if (sD1[mid] >= tm1) hi_ = mid; else lo_ = mid + 1; }
        b1 = lo_;
    } else {
        int j = m;
        while (j > p1 && sD1[j - 1] == tm1) j--;
        b1 = j;
        int lo_ = 0, hi_ = p1;
        while (lo_ < hi_) { int mid = (lo_ + hi_) >> 1; if (sD1[mid] < tm1) hi_ = mid; else lo_ = mid + 1; }
        a1 = lo_;
    }

    const float den0 = sP0[a0] + (S0 - sP0[b0]);
    const float den1 = sP1[a1] + (S1 - sP1[b1]);
    float term = ((pm == i0) ? 0.f : (lo_s0 - __logf(den0)))
               + ((pm == i1) ? 0.f : (lo_s1 - __logf(den1)));

    #pragma unroll
    for (int o = 16; o; o >>= 1) term += __shfl_xor_sync(0xffffffffu, term, o);
    __syncthreads();
    if (lane == 0) warpS0[w] = term;
    __syncthreads();
    if (m == 0) {
        float s = 0.f;
        #pragma unroll
        for (int qq = 0; qq < 16; qq++) s += warpS0[qq];
        atomicAdd(&g_acc, (double)s);
        __threadfence();
        int done = atomicAdd(&g_count, 1);
        if (done == (N_TOT / 2) - 1) {
            double total = atomicAdd(&g_acc, 0.0);
            out[0] = (float)(-total / (double)(N_TOT * (N_TOT - 1)));
        }
    }
}

extern "C" void kernel_launch(void* const* d_in, const int* in_sizes, int n_in,
                              void* d_out, int out_size) {
    const float* wt = (const float*)d_in[0];
    const float* mt = (const float*)d_in[1];
    const float* lw = (const float*)d_in[2];
    const float* lm = (const float*)d_in[3];
    float* out = (float*)d_out;

    gemm_sort_kernel<<<GRID_G, 256>>>(wt, mt, lw, lm);
    loss_kernel<<<N_TOT / 2, N_TOT>>>(lw, lm, out);
}

// round 15
// speedup vs baseline: 1.4349x; 1.0118x over previous
#include <cuda_runtime.h>
#include <cuda_bf16.h>
#include <math.h>
#include <stdint.h>

#define N_TOT 512
#define D_DIM 512

__device__ __align__(16) float g_LO[N_TOT * N_TOT];   // lo = -dist/2
__device__ __align__(16) float g_ys[N_TOT];           // labels sorted ascending
__device__ __align__(16) int   g_perm[N_TOT];         // g_ys[m] = y[g_perm[m]]
__device__ double g_acc;
__device__ int    g_count;

#define NTILES 136         // 16*17/2 upper-triangle 32x32 tiles
__device__ __align__(16) float g_pc[NTILES][2][1024]; // split-K partial C fragments
__device__ __align__(16) float g_pn[NTILES][2][64];   // partial norms (nA 0..31, nB 32..63)
__device__ int g_tc[NTILES];                          // per-tile arrival counter

__device__ __forceinline__ const float* frow(const float* wt, const float* mt, int r) {
    return (r < 256) ? (wt + r * D_DIM) : (mt + (r - 256) * D_DIM);
}
__device__ __forceinline__ float lab(const float* lw, const float* lm, int r) {
    return (r < 256) ? lw[r] : lm[r - 256];
}

// ===================== warp-MMA helpers (HMMA bf16) =====================
__device__ __forceinline__ uint32_t smem_u32(const void* p) {
    uint32_t a;
    asm("{ .reg .u64 t; cvta.to.shared.u64 t, %1; cvt.u32.u64 %0, t; }" : "=r"(a) : "l"(p));
    return a;
}
__device__ __forceinline__ void ldsm4(uint32_t* r, uint32_t addr) {
    asm volatile("ldmatrix.sync.aligned.m8n8.x4.shared.b16 {%0,%1,%2,%3}, [%4];"
                 : "=r"(r[0]), "=r"(r[1]), "=r"(r[2]), "=r"(r[3]) : "r"(addr));
}
__device__ __forceinline__ void mma_bf16(float* c, const uint32_t* a, const uint32_t* b) {
    asm volatile("mma.sync.aligned.m16n8k16.row.col.f32.bf16.bf16.f32 "
                 "{%0,%1,%2,%3}, {%4,%5,%6,%7}, {%8,%9}, {%0,%1,%2,%3};"
                 : "+f"(c[0]), "+f"(c[1]), "+f"(c[2]), "+f"(c[3])
                 : "r"(a[0]), "r"(a[1]), "r"(a[2]), "r"(a[3]), "r"(b[0]), "r"(b[1]));
}
__device__ __forceinline__ void split4(float4 f, uint2& h, uint2& l) {
    __nv_bfloat162 h0 = __floats2bfloat162_rn(f.x, f.y);
    __nv_bfloat162 h1 = __floats2bfloat162_rn(f.z, f.w);
    float2 g0 = __bfloat1622float2(h0), g1 = __bfloat1622float2(h1);
    __nv_bfloat162 l0 = __floats2bfloat162_rn(f.x - g0.x, f.y - g0.y);
    __nv_bfloat162 l1 = __floats2bfloat162_rn(f.z - g1.x, f.w - g1.y);
    h = make_uint2(*(uint32_t*)&h0, *(uint32_t*)&h1);
    l = make_uint2(*(uint32_t*)&l0, *(uint32_t*)&l1);
}

#define STRIDE 40          // bf16 elems per smem row (32 data + 8 pad)
#define BK 32
#define NCHUNK_H 8         // 8 chunks per split-K half
#define NBUF 3
#define NGEMM (NTILES * 2)
#define GRID_G (NGEMM + 4)

struct GemmSmem {
    float nA[32];
    float nB[32];
    union {
        struct {
            unsigned short a_hi[NBUF][32 * STRIDE];
            unsigned short a_lo[NBUF][32 * STRIDE];
            unsigned short b_hi[NBUF][32 * STRIDE];
            unsigned short b_lo[NBUF][32 * STRIDE];
        } buf;
        float stage[32][33];
        float ls[N_TOT];
    } u;
};

// ---------------------------------------------------------------------------
// Kernel 1: 272 split-K HMMA blocks (2 per triangle tile, last-arriver
// combines + epilogue) + 4 sort blocks. 256 threads.
// ---------------------------------------------------------------------------
__global__ void __launch_bounds__(256)
gemm_sort_kernel(const float* __restrict__ wt, const float* __restrict__ mt,
                 const float* __restrict__ lw, const float* __restrict__ lm) {
    __shared__ GemmSmem sm;
    __shared__ int sflag;

    const int t = threadIdx.x;
    const int bid = blockIdx.x;
    const int w = t >> 5, lane = t & 31;

    if (bid < NGEMM) {
        const int tile = bid >> 1;
        const int sid = bid & 1;            // K half
        int ti = 0, base = 0;
        while (base + (16 - ti) <= tile) { base += 16 - ti; ti++; }
        const int tj = ti + (tile - base);
        const int I = ti * 32, J = tj * 32;
        const int k0 = sid * 256;           // this half's starting fp32 column

        const int g = t >> 3, q = t & 7;
        const float* arp = frow(wt, mt, I + g) + k0 + q * 4;
        const float* brp = frow(wt, mt, J + g) + k0 + q * 4;
        float na = 0.f, nb = 0.f;
        const uint32_t se = g * STRIDE + q * 4;

        const int wm = w >> 2, wn = w & 3;
        float c[4] = {};

        const uint32_t a_hi_b = smem_u32(sm.u.buf.a_hi[0]);
        const uint32_t a_lo_b = smem_u32(sm.u.buf.a_lo[0]);
        const uint32_t b_hi_b = smem_u32(sm.u.buf.b_hi[0]);
        const uint32_t b_lo_b = smem_u32(sm.u.buf.b_lo[0]);
        const uint32_t step = 32 * STRIDE * 2;

        const uint32_t a_off = (uint32_t)((wm * 16 + (lane & 15)) * (STRIDE * 2) + ((lane >> 4) & 1) * 16);
        const uint32_t b_off = (uint32_t)((wn * 8 + (lane & 7)) * (STRIDE * 2) + (lane >> 3) * 16);

        float4 Ra, Rb;
        Ra = *(const float4*)arp; Rb = *(const float4*)brp;
        {
            uint2 h, l;
            na += Ra.x*Ra.x + Ra.y*Ra.y + Ra.z*Ra.z + Ra.w*Ra.w;
            split4(Ra, h, l);
            *(uint2*)&sm.u.buf.a_hi[0][se] = h; *(uint2*)&sm.u.buf.a_lo[0][se] = l;
            nb += Rb.x*Rb.x + Rb.y*Rb.y + Rb.z*Rb.z + Rb.w*Rb.w;
            split4(Rb, h, l);
            *(uint2*)&sm.u.buf.b_hi[0][se] = h; *(uint2*)&sm.u.buf.b_lo[0][se] = l;
        }
        Ra = *(const float4*)(arp + BK); Rb = *(const float4*)(brp + BK);

        for (int n = 0; n < NCHUNK_H; n++) {
            const int cur = n % NBUF;
            if (n + 1 < NCHUNK_H) {
                const int nxt = (n + 1) % NBUF;
                uint2 h, l;
                na += Ra.x*Ra.x + Ra.y*Ra.y + Ra.z*Ra.z + Ra.w*Ra.w;
                split4(Ra, h, l);
                *(uint2*)&sm.u.buf.a_hi[nxt][se] = h; *(uint2*)&sm.u.buf.a_lo[nxt][se] = l;
                nb += Rb.x*Rb.x + Rb.y*Rb.y + Rb.z*Rb.z + Rb.w*Rb.w;
                split4(Rb, h, l);
                *(uint2*)&sm.u.buf.b_hi[nxt][se] = h; *(uint2*)&sm.u.buf.b_lo[nxt][se] = l;
            }
            if (n + 2 < NCHUNK_H) {
                const int ko = (n + 2) * BK;
                Ra = *(const float4*)(arp + ko);
                Rb = *(const float4*)(brp + ko);
            }
            __syncthreads();

            uint32_t Bh[4], Bl[4];
            ldsm4(Bh, b_hi_b + cur * step + b_off);
            ldsm4(Bl, b_lo_b + cur * step + b_off);
            #pragma unroll
            for (int ks = 0; ks < 2; ks++) {
                uint32_t Ah[4], Al[4];
                ldsm4(Ah, a_hi_b + cur * step + a_off + ks * 32);
                ldsm4(Al, a_lo_b + cur * step + a_off + ks * 32);
                mma_bf16(c, Ah, Bh + ks * 2);
                mma_bf16(c, Ah, Bl + ks * 2);
                mma_bf16(c, Al, Bh + ks * 2);
            }
        }

        // half-K norms: reduce over the 8 q-threads of each row
        na += __shfl_xor_sync(0xffffffffu, na, 1);
        na += __shfl_xor_sync(0xffffffffu, na, 2);
        na += __shfl_xor_sync(0xffffffffu, na, 4);
        nb += __shfl_xor_sync(0xffffffffu, nb, 1);
        nb += __shfl_xor_sync(0xffffffffu, nb, 2);
        nb += __shfl_xor_sync(0xffffffffu, nb, 4);

        // publish partials; last arriver combines
        *(float4*)&g_pc[tile][sid][t * 4] = make_float4(c[0], c[1], c[2], c[3]);
        if (q == 0) { g_pn[tile][sid][g] = na; g_pn[tile][sid][32 + g] = nb; }
        __threadfence();
        __syncthreads();
        if (t == 0) sflag = atomicAdd(&g_tc[tile], 1);
        __syncthreads();
        if (sflag == 0) return;          // first arriver: done
        __threadfence();                 // acquire other block's stores

        const int o = sid ^ 1;
        float4 oc = *(const float4*)&g_pc[tile][o][t * 4];
        c[0] += oc.x; c[1] += oc.y; c[2] += oc.z; c[3] += oc.w;
        if (q == 0) {
            sm.nA[g] = na + g_pn[tile][o][g];
            sm.nB[g] = nb + g_pn[tile][o][32 + g];
        }
        __syncthreads();

        const int r0 = wm * 16 + (lane >> 2);
        const int cL = wn * 8 + (lane & 3) * 2;
        const float ni0 = sm.nA[r0], ni1 = sm.nA[r0 + 8];
        const float nj0 = sm.nB[cL], nj1 = sm.nB[cL + 1];
        float sq, v00, v01, v10, v11;
        sq = fmaf(-2.f, c[0], ni0 + nj0); v00 = -0.5f * sqrtf(fmaxf(sq, 0.f));
        sq = fmaf(-2.f, c[1], ni0 + nj1); v01 = -0.5f * sqrtf(fmaxf(sq, 0.f));
        sq = fmaf(-2.f, c[2], ni1 + nj0); v10 = -0.5f * sqrtf(fmaxf(sq, 0.f));
        sq = fmaf(-2.f, c[3], ni1 + nj1); v11 = -0.5f * sqrtf(fmaxf(sq, 0.f));
        *(float2*)&g_LO[(I + r0) * N_TOT + J + cL]     = make_float2(v00, v01);
        *(float2*)&g_LO[(I + r0 + 8) * N_TOT + J + cL] = make_float2(v10, v11);

        if (ti != tj) {
            sm.u.stage[r0][cL] = v00;     sm.u.stage[r0][cL + 1] = v01;
            sm.u.stage[r0 + 8][cL] = v10; sm.u.stage[r0 + 8][cL + 1] = v11;
            __syncthreads();
            const int mc = t >> 3;
            const int rg = (t & 7) * 4;
            float4 mo;
            mo.x = sm.u.stage[rg + 0][mc]; mo.y = sm.u.stage[rg + 1][mc];
            mo.z = sm.u.stage[rg + 2][mc]; mo.w = sm.u.stage[rg + 3][mc];
            *(float4*)&g_LO[(J + mc) * N_TOT + I + rg] = mo;
        }
    } else {
        // ---- 4 sort blocks (2 threads/element); resets accumulators ----
        const int sb = bid - NGEMM;
        if (sb == 0 && t == 0) { g_acc = 0.0; g_count = 0; }
        float* ls = sm.u.ls;
        for (int m = t; m < N_TOT; m += 256) ls[m] = lab(lw, lm, m);
        __syncthreads();
        const int e = sb * 128 + (t >> 1);
        const int half = t & 1;
        const float ye = ls[e];
        int rank = 0;
        const float4* L4 = (const float4*)ls + half * 64;
        const int jbase = half * 256;
        #pragma unroll 4
        for (int j4 = 0; j4 < 64; j4++) {
            float4 v = L4[j4];
            int j = jbase + j4 * 4;
            rank += (v.x < ye) || (v.x == ye && (j + 0) < e);
            rank += (v.y < ye) || (v.y == ye && (j + 1) < e);
            rank += (v.z < ye) || (v.z == ye && (j + 2) < e);
            rank += (v.w < ye) || (v.w == ye && (j + 3) < e);
        }
        rank += __shfl_xor_sync(0xffffffffu, rank, 1);
        if (half == 0) { g_ys[rank] = ye; g_perm[rank] = e; }
    }
}

// ---------------------------------------------------------------------------
// Kernel 2: per-row loss — VERBATIM round-8 numerics (rel_err 0.0) + counter reset
// ---------------------------------------------------------------------------
__global__ void __launch_bounds__(N_TOT)
loss_kernel(const float* __restrict__ lw, const float* __restrict__ lm,
            float* __restrict__ out) {
    __shared__ float sLO[N_TOT];
    __shared__ float sY[N_TOT];
    __shared__ float sD[N_TOT];
    __shared__ float sP[N_TOT + 1];
    __shared__ float warpS[16];
    __shared__ int   sp, spos;

    const int i = blockIdx.x;
    const int m = threadIdx.x;
    const int lane = m & 31, w = m >> 5;

    if (i < NTILES && m == 0) g_tc[i] = 0;   // reset split-K counters for next replay

    sLO[m] = g_LO[i * N_TOT + m];
    sY[m]  = g_ys[m];
    const int pm = g_perm[m];
    const float yi = lab(lw, lm, i);
    if (pm == i) spos = m;
    __syncthreads();

    const float tm = fabsf(yi - sY[m]);
    sD[m] = tm;
    if (m == 0) {
        int lo_ = 0, hi_ = N_TOT;
        while (lo_ < hi_) { int mid = (lo_ + hi_) >> 1; if (sY[mid] >= yi) hi_ = mid; else lo_ = mid + 1; }
        sp = lo_;
    }

    const float lo_s = sLO[pm];
    const float e = (pm == i) ? 0.f : __expf(lo_s);

    float v = e;
    #pragma unroll
    for (int o = 1; o < 32; o <<= 1) {
        float nvl = __shfl_up_sync(0xffffffffu, v, o);
        if (lane >= o) v += nvl;
    }
    if (lane == 31) warpS[w] = v;
    __syncthreads();
    if (w == 0) {
        float s = (lane < 16) ? warpS[lane] : 0.f;
        #pragma unroll
        for (int o = 1; o < 16; o <<= 1) {
            float nvl = __shfl_up_sync(0xffffffffu, s, o);
            if (lane >= o) s += nvl;
        }
        if (lane < 16) warpS[lane] = s;
    }
    __syncthreads();
    const float off = (w > 0) ? warpS[w - 1] : 0.f;
    const float S = warpS[15];
    sP[m] = off + v - e;
    if (m == N_TOT - 1) sP[N_TOT] = off + v;
    __syncthreads();

    const int p = sp;
    int a, b;
    if (m < p) {
        int j = m + 1;
        while (j < p && sD[j] == tm) j++;
        a = j;
        int lo_ = p, hi_ = N_TOT;
        while (lo_ < hi_) { int mid = (lo_ + hi_) >> 1; if (sD[mid] >= tm) hi_ = mid; else lo_ = mid + 1; }
        b = lo_;
    } else {
        int j = m;
        while (j > p && sD[j - 1] == tm) j--;
        b = j;
        int lo_ = 0, hi_ = p;
        while (lo_ < hi_) { int mid = (lo_ + hi_) >> 1; if (sD[mid] < tm) hi_ = mid; else lo_ = mid + 1; }
        a = lo_;
    }

    const float denom = sP[a] + (S - sP[b]);
    float term = (m == spos) ? 0.f : (lo_s - __logf(denom));

    #pragma unroll
    for (int o = 16; o; o >>= 1) term += __shfl_xor_sync(0xffffffffu, term, o);
    __syncthreads();
    if (lane == 0) warpS[w] = term;
    __syncthreads();
    if (m == 0) {
        float s = 0.f;
        #pragma unroll
        for (int qq = 0; qq < 16; qq++) s += warpS[qq];
        atomicAdd(&g_acc, (double)s);
        __threadfence();
        int done = atomicAdd(&g_count, 1);
        if (done == N_TOT - 1) {
            double total = atomicAdd(&g_acc, 0.0);
            out[0] = (float)(-total / (double)(N_TOT * (N_TOT - 1)));
        }
    }
}

extern "C" void kernel_launch(void* const* d_in, const int* in_sizes, int n_in,
                              void* d_out, int out_size) {
    const float* wt = (const float*)d_in[0];
    const float* mt = (const float*)d_in[1];
    const float* lw = (const float*)d_in[2];
    const float* lm = (const float*)d_in[3];
    float* out = (float*)d_out;

    gemm_sort_kernel<<<GRID_G, 256>>>(wt, mt, lw, lm);
    loss_kernel<<<N_TOT, N_TOT>>>(lw, lm, out);
}